// round 1
// baseline (speedup 1.0000x reference)
#include <cuda_runtime.h>

// Geometry: (B=1, C=3, f=16, H=720, W=1280) -> 48 planes of 720x1280 per tensor.
#define Wd 1280
#define Hd 720
#define NPLANE (Hd * Wd)          // 921600
#define PLANES 48
#define NTOT (PLANES * NPLANE)    // 44,236,800 elements per tensor

// Scratch ping-pong buffers: [hq chain | lq chain] each, 2 * NTOT floats.
__device__ float g_bufA[2 * NTOT];
__device__ float g_bufB[2 * NTOT];

// Separable blur, one wavelet level, radius R (dilation), replicate padding.
// Tile: 64 wide x 40 tall output per CTA, 256 threads.
// blockIdx.z in [0,96): z<48 -> hq chain plane z; else lq chain plane z-48.
template <int R>
__global__ void __launch_bounds__(256)
blur_kernel(const float* __restrict__ srcHq, const float* __restrict__ srcLq,
            float* __restrict__ dstHq, float* __restrict__ dstLq)
{
    constexpr int TW = 64, TH = 40;
    constexpr int IW = TW + 2 * R;    // input tile width (with halo)
    constexpr int IH = TH + 2 * R;    // input tile height (with halo)

    __shared__ float s_in[IH * IW];   // raw input tile
    __shared__ float s_h [IH * TW];   // after horizontal pass

    const int z = blockIdx.z;
    const float* __restrict__ src;
    float* __restrict__ dst;
    if (z < PLANES) { src = srcHq + z * NPLANE;             dst = dstHq + z * NPLANE; }
    else            { src = srcLq + (z - PLANES) * NPLANE;  dst = dstLq + (z - PLANES) * NPLANE; }

    const int tx0 = blockIdx.x * TW;
    const int ty0 = blockIdx.y * TH;
    const int tid = threadIdx.x;

    // Phase 1: load input tile with replicate-clamped coordinates.
    #pragma unroll 4
    for (int i = tid; i < IH * IW; i += 256) {
        int iy = i / IW, ix = i - iy * IW;
        int gy = ty0 - R + iy; gy = gy < 0 ? 0 : (gy >= Hd ? Hd - 1 : gy);
        int gx = tx0 - R + ix; gx = gx < 0 ? 0 : (gx >= Wd ? Wd - 1 : gx);
        s_in[i] = __ldg(src + gy * Wd + gx);
    }
    __syncthreads();

    // Phase 2: horizontal [1/4, 1/2, 1/4] with dilation R.
    #pragma unroll 4
    for (int i = tid; i < IH * TW; i += 256) {
        int iy = i / TW, ix = i - iy * TW;
        const float* row = &s_in[iy * IW + ix];
        s_h[i] = 0.25f * (row[0] + row[2 * R]) + 0.5f * row[R];
    }
    __syncthreads();

    // Phase 3: vertical pass + global store.
    #pragma unroll 4
    for (int i = tid; i < TH * TW; i += 256) {
        int oy = i / TW, ox = i - oy * TW;
        float v = 0.25f * (s_h[oy * TW + ox] + s_h[(oy + 2 * R) * TW + ox])
                + 0.50f * s_h[(oy + R) * TW + ox];
        int gy = ty0 + oy, gx = tx0 + ox;
        if (gy < Hd) dst[gy * Wd + gx] = v;
    }
}

// out = clip(hq - low5(hq) + low5(lq), -1, 1), vectorized float4.
__global__ void __launch_bounds__(256)
combine_kernel(const float4* __restrict__ hq, const float4* __restrict__ lowHq,
               const float4* __restrict__ lowLq, float4* __restrict__ out, int n4)
{
    int i = blockIdx.x * blockDim.x + threadIdx.x;
    if (i >= n4) return;
    float4 a = hq[i], b = lowHq[i], c = lowLq[i];
    float4 r;
    r.x = fminf(fmaxf(a.x - b.x + c.x, -1.0f), 1.0f);
    r.y = fminf(fmaxf(a.y - b.y + c.y, -1.0f), 1.0f);
    r.z = fminf(fmaxf(a.z - b.z + c.z, -1.0f), 1.0f);
    r.w = fminf(fmaxf(a.w - b.w + c.w, -1.0f), 1.0f);
    out[i] = r;
}

extern "C" void kernel_launch(void* const* d_in, const int* in_sizes, int n_in,
                              void* d_out, int out_size)
{
    const float* hq = (const float*)d_in[0];
    const float* lq = (const float*)d_in[1];
    float* out = (float*)d_out;

    float *A, *B;
    cudaGetSymbolAddress((void**)&A, g_bufA);
    cudaGetSymbolAddress((void**)&B, g_bufB);

    dim3 block(256);
    dim3 grid(Wd / 64, Hd / 40, 2 * PLANES);   // (20, 18, 96)

    // Level 1..5: low chain for both tensors, ping-pong A <-> B.
    blur_kernel<1> <<<grid, block>>>(hq, lq,       A, A + NTOT);
    blur_kernel<2> <<<grid, block>>>(A, A + NTOT,  B, B + NTOT);
    blur_kernel<4> <<<grid, block>>>(B, B + NTOT,  A, A + NTOT);
    blur_kernel<8> <<<grid, block>>>(A, A + NTOT,  B, B + NTOT);
    blur_kernel<16><<<grid, block>>>(B, B + NTOT,  A, A + NTOT);

    // Combine: out = clip(hq - lowHq + lowLq, -1, 1)
    int n4 = NTOT / 4;
    combine_kernel<<<(n4 + 255) / 256, 256>>>(
        (const float4*)hq, (const float4*)A, (const float4*)(A + NTOT),
        (float4*)out, n4);
}

// round 2
// speedup vs baseline: 1.7160x; 1.7160x over previous
#include <cuda_runtime.h>

#define Wd 1280
#define WV 320                 // float4 per row
#define Hd 720
#define NPLANE (Hd * Wd)
#define NPV (Hd * WV)          // float4 per plane
#define PLANES 48
#define NTOT (PLANES * NPLANE) // floats per tensor
#define NV4 (NTOT / 4)         // float4 per tensor
#define TH 16
#define NBANDS (Hd / TH)       // 45

// Ping-pong scratch: [hq chain | lq chain]
__device__ float g_bufA[2 * NTOT];
__device__ float g_bufB[2 * NTOT];

__device__ __forceinline__ float4 vmix(float4 a, float4 b, float4 d) {
    float4 o;
    o.x = fmaf(0.25f, a.x + d.x, 0.5f * b.x);
    o.y = fmaf(0.25f, a.y + d.y, 0.5f * b.y);
    o.z = fmaf(0.25f, a.z + d.z, 0.5f * b.z);
    o.w = fmaf(0.25f, a.w + d.w, 0.5f * b.w);
    return o;
}

// Vertical [1/4,1/2,1/4] with dilation R, replicate rows, band of TH rows -> smem
template <int R>
__device__ __forceinline__ void vpass(const float4* __restrict__ src, int y0, int c,
                                      float4* __restrict__ s_v) {
    bool interior = (y0 >= R) && (y0 + TH - 1 + R < Hd);
    if (interior) {
        const float4* p = src + (size_t)(y0 - R) * WV + c;
        #pragma unroll
        for (int r = 0; r < TH; r++)
            s_v[r * WV + c] = vmix(p[(size_t)r * WV], p[(size_t)(r + R) * WV],
                                   p[(size_t)(r + 2 * R) * WV]);
    } else {
        #pragma unroll
        for (int r = 0; r < TH; r++) {
            int y = y0 + r;
            int ym = (y - R < 0) ? 0 : y - R;
            int yp = (y + R >= Hd) ? Hd - 1 : y + R;
            s_v[r * WV + c] = vmix(src[(size_t)ym * WV + c], src[(size_t)y * WV + c],
                                   src[(size_t)yp * WV + c]);
        }
    }
}

// Horizontal [1/4,1/2,1/4] with dilation R on one smem row (full width, replicate cols)
template <int R>
__device__ __forceinline__ float4 hmix(const float4* __restrict__ row, int c) {
    float4 ce = row[c];
    float4 xm, xp;
    if constexpr (R >= 4) {
        constexpr int RV = R / 4;
        if (c >= RV) xm = row[c - RV];
        else { float v = row[0].x; xm = make_float4(v, v, v, v); }
        if (c + RV < WV) xp = row[c + RV];
        else { float v = row[WV - 1].w; xp = make_float4(v, v, v, v); }
    } else if constexpr (R == 1) {
        if (c > 0) { float4 l = row[c - 1]; xm = make_float4(l.w, ce.x, ce.y, ce.z); }
        else xm = make_float4(ce.x, ce.x, ce.y, ce.z);
        if (c < WV - 1) { float4 rr = row[c + 1]; xp = make_float4(ce.y, ce.z, ce.w, rr.x); }
        else xp = make_float4(ce.y, ce.z, ce.w, ce.w);
    } else { // R == 2
        if (c > 0) { float4 l = row[c - 1]; xm = make_float4(l.z, l.w, ce.x, ce.y); }
        else xm = make_float4(ce.x, ce.x, ce.x, ce.y);
        if (c < WV - 1) { float4 rr = row[c + 1]; xp = make_float4(ce.z, ce.w, rr.x, rr.y); }
        else xp = make_float4(ce.z, ce.w, ce.w, ce.w);
    }
    float4 o;
    o.x = fmaf(0.25f, xm.x + xp.x, 0.5f * ce.x);
    o.y = fmaf(0.25f, xm.y + xp.y, 0.5f * ce.y);
    o.z = fmaf(0.25f, xm.z + xp.z, 0.5f * ce.z);
    o.w = fmaf(0.25f, xm.w + xp.w, 0.5f * ce.w);
    return o;
}

// One wavelet level for both chains. blockIdx.y in [0,96): <48 -> hq chain.
template <int R>
__global__ void __launch_bounds__(320)
blur_band(const float4* __restrict__ srcHq, const float4* __restrict__ srcLq,
          float4* __restrict__ dstHq, float4* __restrict__ dstLq) {
    extern __shared__ float4 s_v[];
    const int c = threadIdx.x;
    const int y0 = blockIdx.x * TH;
    const int z = blockIdx.y;
    const float4* src;
    float4* dst;
    if (z < PLANES) { src = srcHq + (size_t)z * NPV; dst = dstHq + (size_t)z * NPV; }
    else { src = srcLq + (size_t)(z - PLANES) * NPV; dst = dstLq + (size_t)(z - PLANES) * NPV; }

    vpass<R>(src, y0, c, s_v);
    __syncthreads();
    #pragma unroll
    for (int r = 0; r < TH; r++)
        dst[(size_t)(y0 + r) * WV + c] = hmix<R>(s_v + r * WV, c);
}

// Level 5 for both chains + fused combine: out = clip(hq - low5(hq) + low5(lq), -1, 1)
__global__ void __launch_bounds__(320, 2)
final_band(const float4* __restrict__ lowHq, const float4* __restrict__ lowLq,
           const float4* __restrict__ hq, float4* __restrict__ out) {
    constexpr int R = 16;
    extern __shared__ float4 s_v[];
    const int c = threadIdx.x;
    const int y0 = blockIdx.x * TH;
    const int z = blockIdx.y;
    const float4* sH = lowHq + (size_t)z * NPV;
    const float4* sL = lowLq + (size_t)z * NPV;
    const float4* hp = hq + (size_t)z * NPV;
    float4* op = out + (size_t)z * NPV;

    // hq chain -> registers
    vpass<R>(sH, y0, c, s_v);
    __syncthreads();
    float4 acc[TH];
    #pragma unroll
    for (int r = 0; r < TH; r++) acc[r] = hmix<R>(s_v + r * WV, c);
    __syncthreads();

    // lq chain -> combine + store
    vpass<R>(sL, y0, c, s_v);
    __syncthreads();
    #pragma unroll
    for (int r = 0; r < TH; r++) {
        float4 lo = hmix<R>(s_v + r * WV, c);
        float4 h = hp[(size_t)(y0 + r) * WV + c];
        float4 o;
        o.x = fminf(fmaxf(h.x - acc[r].x + lo.x, -1.0f), 1.0f);
        o.y = fminf(fmaxf(h.y - acc[r].y + lo.y, -1.0f), 1.0f);
        o.z = fminf(fmaxf(h.z - acc[r].z + lo.z, -1.0f), 1.0f);
        o.w = fminf(fmaxf(h.w - acc[r].w + lo.w, -1.0f), 1.0f);
        op[(size_t)(y0 + r) * WV + c] = o;
    }
}

extern "C" void kernel_launch(void* const* d_in, const int* in_sizes, int n_in,
                              void* d_out, int out_size) {
    const float4* hq = (const float4*)d_in[0];
    const float4* lq = (const float4*)d_in[1];
    float4* out = (float4*)d_out;

    float *Af, *Bf;
    cudaGetSymbolAddress((void**)&Af, g_bufA);
    cudaGetSymbolAddress((void**)&Bf, g_bufB);
    float4* A = (float4*)Af;
    float4* B = (float4*)Bf;

    const size_t smem = (size_t)TH * WV * sizeof(float4);  // 80 KB
    cudaFuncSetAttribute(blur_band<1>, cudaFuncAttributeMaxDynamicSharedMemorySize, (int)smem);
    cudaFuncSetAttribute(blur_band<2>, cudaFuncAttributeMaxDynamicSharedMemorySize, (int)smem);
    cudaFuncSetAttribute(blur_band<4>, cudaFuncAttributeMaxDynamicSharedMemorySize, (int)smem);
    cudaFuncSetAttribute(blur_band<8>, cudaFuncAttributeMaxDynamicSharedMemorySize, (int)smem);
    cudaFuncSetAttribute(final_band,   cudaFuncAttributeMaxDynamicSharedMemorySize, (int)smem);

    dim3 g(NBANDS, 2 * PLANES);
    blur_band<1><<<g, 320, smem>>>(hq, lq, A, A + NV4);
    blur_band<2><<<g, 320, smem>>>(A, A + NV4, B, B + NV4);
    blur_band<4><<<g, 320, smem>>>(B, B + NV4, A, A + NV4);
    blur_band<8><<<g, 320, smem>>>(A, A + NV4, B, B + NV4);

    dim3 gf(NBANDS, PLANES);
    final_band<<<gf, 320, smem>>>(B, B + NV4, hq, out);
}

// round 4
// speedup vs baseline: 1.7913x; 1.0439x over previous
#include <cuda_runtime.h>

#define Wd 1280
#define WV 320                 // float4 per row
#define Hd 720
#define NPV (Hd * WV)          // float4 per plane
#define PLANES 48
#define NV4 (PLANES * NPV)     // float4 per tensor

// Ping-pong scratch: [hq chain | lq chain]
__device__ float4 g_bufA[2 * NV4];
__device__ float4 g_bufB[2 * NV4];

__device__ __forceinline__ int iclamp(int v, int lo, int hi) {
    return v < lo ? lo : (v > hi ? hi : v);
}
__device__ __forceinline__ float4 splat4(float v) { return make_float4(v, v, v, v); }

// 0.25*(a+d) + 0.5*b  (the [1/4,1/2,1/4] tap, both axes)
__device__ __forceinline__ float4 vmix(float4 a, float4 b, float4 d) {
    float4 o;
    o.x = fmaf(0.25f, a.x + d.x, 0.5f * b.x);
    o.y = fmaf(0.25f, a.y + d.y, 0.5f * b.y);
    o.z = fmaf(0.25f, a.z + d.z, 0.5f * b.z);
    o.w = fmaf(0.25f, a.w + d.w, 0.5f * b.w);
    return o;
}

// Horizontal mix, pixel dilation R, full-width (WV float4) row, replicate edges.
template <int R>
__device__ __forceinline__ float4 hmix(const float4* __restrict__ row, int c) {
    float4 ce = row[c];
    float4 xm, xp;
    if constexpr (R >= 4) {
        constexpr int RV = R / 4;
        if (c >= RV) xm = row[c - RV]; else xm = splat4(row[0].x);
        if (c + RV < WV) xp = row[c + RV]; else xp = splat4(row[WV - 1].w);
    } else if constexpr (R == 1) {
        if (c > 0) { float4 l = row[c - 1]; xm = make_float4(l.w, ce.x, ce.y, ce.z); }
        else xm = make_float4(ce.x, ce.x, ce.y, ce.z);
        if (c < WV - 1) { float4 rr = row[c + 1]; xp = make_float4(ce.y, ce.z, ce.w, rr.x); }
        else xp = make_float4(ce.y, ce.z, ce.w, ce.w);
    } else { // R == 2
        if (c > 0) { float4 l = row[c - 1]; xm = make_float4(l.z, l.w, ce.x, ce.y); }
        else xm = make_float4(ce.x, ce.x, ce.x, ce.y);
        if (c < WV - 1) { float4 rr = row[c + 1]; xp = make_float4(ce.z, ce.w, rr.x, rr.y); }
        else xp = make_float4(ce.z, ce.w, ce.w, ce.w);
    }
    return vmix(xm, ce, xp);
}

// ───────── Kernel A: levels 1+2 fused (R=1 then R=2), full-width bands ─────────
// Band TH_A=8 output rows; low1 buffer RB_A = 12 rows. block (320,2) = 640 thr.
#define TH_A 8
#define RB_A 12
__global__ void __launch_bounds__(640)
levelAB(const float4* __restrict__ srcHq, const float4* __restrict__ srcLq,
        float4* __restrict__ dstHq, float4* __restrict__ dstLq) {
    extern __shared__ float4 s[];  // [RB_A][WV]
    const int c = threadIdx.x, ty = threadIdx.y;
    const int y0 = blockIdx.x * TH_A;
    const int z = blockIdx.y;
    const float4* src;
    float4* dst;
    if (z < PLANES) { src = srcHq + (size_t)z * NPV; dst = dstHq + (size_t)z * NPV; }
    else { src = srcLq + (size_t)(z - PLANES) * NPV; dst = dstLq + (size_t)(z - PLANES) * NPV; }

    // stage 1a: vertical R=1 (buffer row i holds image row clamp(y0-2+i))
    for (int i = ty; i < RB_A; i += 2) {
        int yi = iclamp(y0 - 2 + i, 0, Hd - 1);
        int ym = iclamp(yi - 1, 0, Hd - 1), yp = iclamp(yi + 1, 0, Hd - 1);
        s[i * WV + c] = vmix(__ldg(src + (size_t)ym * WV + c),
                             __ldg(src + (size_t)yi * WV + c),
                             __ldg(src + (size_t)yp * WV + c));
    }
    __syncthreads();
    // stage 1b: horizontal R=1, in-place (2-sync)
    float4 t[6]; int k = 0;
    for (int i = ty; i < RB_A; i += 2) t[k++] = hmix<1>(s + i * WV, c);
    __syncthreads();
    k = 0;
    for (int i = ty; i < RB_A; i += 2) s[i * WV + c] = t[k++];
    __syncthreads();
    // stage 2a: vertical R=2 on low1 buffer
    float4 u[4]; k = 0;
    for (int r = ty; r < TH_A; r += 2)
        u[k++] = vmix(s[r * WV + c], s[(r + 2) * WV + c], s[(r + 4) * WV + c]);
    __syncthreads();
    k = 0;
    for (int r = ty; r < TH_A; r += 2) s[r * WV + c] = u[k++];
    __syncthreads();
    // stage 2b: horizontal R=2, store
    for (int r = ty; r < TH_A; r += 2)
        dst[(size_t)(y0 + r) * WV + c] = hmix<2>(s + r * WV, c);
}

// ───────── Kernel B: levels 3+4 fused (R=4 then R=8), x-tiled ─────────
// Output tile 80 float4 x 16 rows. Buffer 86 float4 x 32 rows. block (86,8)=688.
#define TH_B 16
#define RB_B 32
#define TW_B 80
#define VW_B 86
__global__ void __launch_bounds__(704)
levelCD(const float4* __restrict__ srcHq, const float4* __restrict__ srcLq,
        float4* __restrict__ dstHq, float4* __restrict__ dstLq) {
    extern __shared__ float4 s[];  // [RB_B][VW_B]
    const int c = threadIdx.x, ty = threadIdx.y;
    const int tx0v = blockIdx.x * TW_B;
    const int y0 = blockIdx.y * TH_B;
    const int z = blockIdx.z;
    const float4* src;
    float4* dst;
    if (z < PLANES) { src = srcHq + (size_t)z * NPV; dst = dstHq + (size_t)z * NPV; }
    else { src = srcLq + (size_t)(z - PLANES) * NPV; dst = dstLq + (size_t)(z - PLANES) * NPV; }

    const int jv = tx0v - 3 + c;
    const int gx = iclamp(jv, 0, WV - 1);

    // stage 1a: vertical R=4 from GMEM (buffer row i <-> image row clamp(y0-8+i))
    for (int i = ty; i < RB_B; i += 8) {
        int yi = iclamp(y0 - 8 + i, 0, Hd - 1);
        int ym = iclamp(yi - 4, 0, Hd - 1), yp = iclamp(yi + 4, 0, Hd - 1);
        float4 v = vmix(__ldg(src + (size_t)ym * WV + gx),
                        __ldg(src + (size_t)yi * WV + gx),
                        __ldg(src + (size_t)yp * WV + gx));
        if (jv < 0) v = splat4(v.x);
        else if (jv > WV - 1) v = splat4(v.w);
        s[i * VW_B + c] = v;
    }
    __syncthreads();
    // stage 1b: horizontal R=4 (aligned +-1 float4), in-place, cols 1..84
    float4 t[4];
    if (c >= 1 && c <= 84) {
        int k = 0;
        for (int i = ty; i < RB_B; i += 8)
            t[k++] = vmix(s[i * VW_B + c - 1], s[i * VW_B + c], s[i * VW_B + c + 1]);
    }
    __syncthreads();
    if (c >= 1 && c <= 84) {
        int k = 0;
        for (int i = ty; i < RB_B; i += 8) s[i * VW_B + c] = t[k++];
    }
    __syncthreads();
    // edge fixup: out-of-image halo cols of low3 must be splat(pad), not formula
    if (tx0v == 0 && (c == 1 || c == 2)) {
        for (int i = ty; i < RB_B; i += 8) s[i * VW_B + c] = splat4(s[i * VW_B + 3].x);
    } else if (tx0v == (WV - TW_B) && (c == 83 || c == 84)) {
        for (int i = ty; i < RB_B; i += 8) s[i * VW_B + c] = splat4(s[i * VW_B + 82].w);
    }
    __syncthreads();
    // stage 2a: vertical R=8 on low3 buffer, cols 1..84
    float4 u[2];
    if (c >= 1 && c <= 84) {
        int k = 0;
        for (int r = ty; r < TH_B; r += 8)
            u[k++] = vmix(s[r * VW_B + c], s[(r + 8) * VW_B + c], s[(r + 16) * VW_B + c]);
    }
    __syncthreads();
    if (c >= 1 && c <= 84) {
        int k = 0;
        for (int r = ty; r < TH_B; r += 8) s[r * VW_B + c] = u[k++];
    }
    __syncthreads();
    // stage 2b: horizontal R=8 (+-2 float4), out col c (0..79) <-> buffer col c+3
    if (c < TW_B) {
        for (int r = ty; r < TH_B; r += 8) {
            float4 o = vmix(s[r * VW_B + c + 1], s[r * VW_B + c + 3], s[r * VW_B + c + 5]);
            dst[(size_t)(y0 + r) * WV + tx0v + c] = o;
        }
    }
}

// ───────── Kernel C: level 5 (R=16) for both chains + combine ─────────
#define TH_C 8
__global__ void __launch_bounds__(640)
final5(const float4* __restrict__ lowHq, const float4* __restrict__ lowLq,
       const float4* __restrict__ hq, float4* __restrict__ out) {
    extern __shared__ float4 s[];  // [TH_C][WV]
    const int c = threadIdx.x, ty = threadIdx.y;
    const int y0 = blockIdx.x * TH_C;
    const int z = blockIdx.y;
    const float4* sH = lowHq + (size_t)z * NPV;
    const float4* sL = lowLq + (size_t)z * NPV;
    const float4* hp = hq + (size_t)z * NPV;
    float4* op = out + (size_t)z * NPV;

    // hq chain
    for (int r = ty; r < TH_C; r += 2) {
        int y = y0 + r;
        int ym = iclamp(y - 16, 0, Hd - 1), yp = iclamp(y + 16, 0, Hd - 1);
        s[r * WV + c] = vmix(__ldg(sH + (size_t)ym * WV + c),
                             __ldg(sH + (size_t)y * WV + c),
                             __ldg(sH + (size_t)yp * WV + c));
    }
    __syncthreads();
    float4 acc[4];
    int k = 0;
    for (int r = ty; r < TH_C; r += 2) acc[k++] = hmix<16>(s + r * WV, c);
    __syncthreads();
    // lq chain + combine
    for (int r = ty; r < TH_C; r += 2) {
        int y = y0 + r;
        int ym = iclamp(y - 16, 0, Hd - 1), yp = iclamp(y + 16, 0, Hd - 1);
        s[r * WV + c] = vmix(__ldg(sL + (size_t)ym * WV + c),
                             __ldg(sL + (size_t)y * WV + c),
                             __ldg(sL + (size_t)yp * WV + c));
    }
    __syncthreads();
    k = 0;
    for (int r = ty; r < TH_C; r += 2) {
        float4 lo = hmix<16>(s + r * WV, c);
        float4 h = __ldg(hp + (size_t)(y0 + r) * WV + c);
        float4 a = acc[k++];
        float4 o;
        o.x = fminf(fmaxf(h.x - a.x + lo.x, -1.0f), 1.0f);
        o.y = fminf(fmaxf(h.y - a.y + lo.y, -1.0f), 1.0f);
        o.z = fminf(fmaxf(h.z - a.z + lo.z, -1.0f), 1.0f);
        o.w = fminf(fmaxf(h.w - a.w + lo.w, -1.0f), 1.0f);
        op[(size_t)(y0 + r) * WV + c] = o;
    }
}

extern "C" void kernel_launch(void* const* d_in, const int* in_sizes, int n_in,
                              void* d_out, int out_size) {
    const float4* hq = (const float4*)d_in[0];
    const float4* lq = (const float4*)d_in[1];
    float4* out = (float4*)d_out;

    float4 *A, *B;
    cudaGetSymbolAddress((void**)&A, g_bufA);
    cudaGetSymbolAddress((void**)&B, g_bufB);

    const int smemA = RB_A * WV * sizeof(float4);    // 60 KB
    const int smemB = RB_B * VW_B * sizeof(float4);  // 43 KB
    const int smemC = TH_C * WV * sizeof(float4);    // 40 KB
    cudaFuncSetAttribute(levelAB, cudaFuncAttributeMaxDynamicSharedMemorySize, smemA);
    cudaFuncSetAttribute(levelCD, cudaFuncAttributeMaxDynamicSharedMemorySize, smemB);
    cudaFuncSetAttribute(final5,  cudaFuncAttributeMaxDynamicSharedMemorySize, smemC);

    // levels 1+2: inputs -> A (low2, both chains)
    levelAB<<<dim3(Hd / TH_A, 2 * PLANES), dim3(WV, 2), smemA>>>(hq, lq, A, A + NV4);
    // levels 3+4: A -> B (low4)
    levelCD<<<dim3(WV / TW_B, Hd / TH_B, 2 * PLANES), dim3(VW_B, 8), smemB>>>(
        A, A + NV4, B, B + NV4);
    // level 5 + combine
    final5<<<dim3(Hd / TH_C, PLANES), dim3(WV, 2), smemC>>>(B, B + NV4, hq, out);
}

// round 5
// speedup vs baseline: 2.0458x; 1.1420x over previous
#include <cuda_runtime.h>

#define Wd 1280
#define WV 320                 // float4 per row
#define Hd 720
#define NPV (Hd * WV)          // float4 per plane
#define PLANES 48
#define NV4 (PLANES * NPV)     // float4 per tensor
#define TH 8
#define NB (Hd / TH)           // 90 bands

// Ping-pong scratch: [hq chain | lq chain]
__device__ float4 g_bufA[2 * NV4];
__device__ float4 g_bufB[2 * NV4];

__device__ __forceinline__ int iclamp(int v, int lo, int hi) {
    return v < lo ? lo : (v > hi ? hi : v);
}
__device__ __forceinline__ float4 splat4(float v) { return make_float4(v, v, v, v); }

// 0.25*(a+d) + 0.5*b
__device__ __forceinline__ float4 vmix(float4 a, float4 b, float4 d) {
    float4 o;
    o.x = fmaf(0.25f, a.x + d.x, 0.5f * b.x);
    o.y = fmaf(0.25f, a.y + d.y, 0.5f * b.y);
    o.z = fmaf(0.25f, a.z + d.z, 0.5f * b.z);
    o.w = fmaf(0.25f, a.w + d.w, 0.5f * b.w);
    return o;
}

// Fused two-level tap: [1,2,3,4,3,2,1]/16
__device__ __forceinline__ float t7(float a0, float a1, float a2, float a3,
                                    float a4, float a5, float a6) {
    return fmaf(0.25f, a3, fmaf(0.1875f, a2 + a4,
           fmaf(0.125f, a1 + a5, 0.0625f * (a0 + a6))));
}
__device__ __forceinline__ float4 f7(float4 a0, float4 a1, float4 a2, float4 a3,
                                     float4 a4, float4 a5, float4 a6) {
    float4 o;
    o.x = t7(a0.x, a1.x, a2.x, a3.x, a4.x, a5.x, a6.x);
    o.y = t7(a0.y, a1.y, a2.y, a3.y, a4.y, a5.y, a6.y);
    o.z = t7(a0.z, a1.z, a2.z, a3.z, a4.z, a5.z, a6.z);
    o.w = t7(a0.w, a1.w, a2.w, a3.w, a4.w, a5.w, a6.w);
    return o;
}

// ── Exact per-level vertical (border CTAs): V_{2R}(V_R(src)) with row clamps ──
template <int RS>
__device__ __forceinline__ float4 v1tap(const float4* __restrict__ src, int q, int c) {
    q = iclamp(q, 0, Hd - 1);
    int ym = iclamp(q - RS, 0, Hd - 1), yp = iclamp(q + RS, 0, Hd - 1);
    return vmix(src[(size_t)ym * WV + c], src[(size_t)q * WV + c],
                src[(size_t)yp * WV + c]);
}
template <int RS>
__device__ __forceinline__ float4 vv_exact(const float4* __restrict__ src, int y, int c) {
    return vmix(v1tap<RS>(src, y - 2 * RS, c), v1tap<RS>(src, y, c),
                v1tap<RS>(src, y + 2 * RS, c));
}

// ── Exact per-level horizontal (border cols), scalar on a full-width smem row ──
template <int RS>
__device__ __forceinline__ float hh_lh(const float* row, int q) {
    q = iclamp(q, 0, Wd - 1);
    return fmaf(0.25f, row[iclamp(q - RS, 0, Wd - 1)] + row[iclamp(q + RS, 0, Wd - 1)],
                0.5f * row[q]);
}
template <int RS>
__device__ __forceinline__ float hh_exact_px(const float* row, int p) {
    return fmaf(0.25f, hh_lh<RS>(row, iclamp(p - 2 * RS, 0, Wd - 1)) +
                        hh_lh<RS>(row, iclamp(p + 2 * RS, 0, Wd - 1)),
                0.5f * hh_lh<RS>(row, p));
}

// ───────── Kernel A: levels 1+2 fused (fused VV R=1, then fused HH R=1) ─────────
__global__ void __launch_bounds__(640)
levelAB(const float4* __restrict__ srcHq, const float4* __restrict__ srcLq,
        float4* __restrict__ dstHq, float4* __restrict__ dstLq) {
    __shared__ float4 s[TH * WV];  // 40 KB static
    const int c = threadIdx.x, ty = threadIdx.y;
    const int y0 = blockIdx.x * TH;
    const int z = blockIdx.y;
    const float4* src;
    float4* dst;
    if (z < PLANES) { src = srcHq + (size_t)z * NPV; dst = dstHq + (size_t)z * NPV; }
    else { src = srcLq + (size_t)(z - PLANES) * NPV; dst = dstLq + (size_t)(z - PLANES) * NPV; }

    const bool interior = (y0 >= 3) && (y0 + TH - 1 + 3 < Hd);
    if (interior) {
        #pragma unroll
        for (int r = ty; r < TH; r += 2) {
            const float4* p = src + (size_t)(y0 + r - 3) * WV + c;
            s[r * WV + c] = f7(p[0], p[WV], p[2 * WV], p[3 * WV],
                               p[4 * WV], p[5 * WV], p[6 * WV]);
        }
    } else {
        #pragma unroll
        for (int r = ty; r < TH; r += 2)
            s[r * WV + c] = vv_exact<1>(src, y0 + r, c);
    }
    __syncthreads();
    #pragma unroll
    for (int r = ty; r < TH; r += 2) {
        const float4* row = s + r * WV;
        float4 o;
        if (c >= 1 && c <= WV - 2) {
            float4 L = row[c - 1], C = row[c], R = row[c + 1];
            o.x = t7(L.y, L.z, L.w, C.x, C.y, C.z, C.w);
            o.y = t7(L.z, L.w, C.x, C.y, C.z, C.w, R.x);
            o.z = t7(L.w, C.x, C.y, C.z, C.w, R.x, R.y);
            o.w = t7(C.x, C.y, C.z, C.w, R.x, R.y, R.z);
        } else {
            const float* rf = (const float*)row;
            int p0 = c * 4;
            o.x = hh_exact_px<1>(rf, p0);
            o.y = hh_exact_px<1>(rf, p0 + 1);
            o.z = hh_exact_px<1>(rf, p0 + 2);
            o.w = hh_exact_px<1>(rf, p0 + 3);
        }
        dst[(size_t)(y0 + r) * WV + c] = o;
    }
}

// ───────── Kernel B: levels 3+4 fused (fused VV R=4, fused HH R=4) ─────────
__global__ void __launch_bounds__(640)
levelCD(const float4* __restrict__ srcHq, const float4* __restrict__ srcLq,
        float4* __restrict__ dstHq, float4* __restrict__ dstLq) {
    __shared__ float4 s[TH * WV];  // 40 KB static
    const int c = threadIdx.x, ty = threadIdx.y;
    const int y0 = blockIdx.x * TH;
    const int z = blockIdx.y;
    const float4* src;
    float4* dst;
    if (z < PLANES) { src = srcHq + (size_t)z * NPV; dst = dstHq + (size_t)z * NPV; }
    else { src = srcLq + (size_t)(z - PLANES) * NPV; dst = dstLq + (size_t)(z - PLANES) * NPV; }

    const bool interior = (y0 >= 12) && (y0 + TH - 1 + 12 < Hd);
    if (interior) {
        #pragma unroll
        for (int r = ty; r < TH; r += 2) {
            const float4* p = src + (size_t)(y0 + r - 12) * WV + c;
            s[r * WV + c] = f7(p[0], p[4 * WV], p[8 * WV], p[12 * WV],
                               p[16 * WV], p[20 * WV], p[24 * WV]);
        }
    } else {
        #pragma unroll
        for (int r = ty; r < TH; r += 2)
            s[r * WV + c] = vv_exact<4>(src, y0 + r, c);
    }
    __syncthreads();
    #pragma unroll
    for (int r = ty; r < TH; r += 2) {
        const float4* row = s + r * WV;
        float4 o;
        if (c >= 3 && c <= WV - 4) {
            o = f7(row[c - 3], row[c - 2], row[c - 1], row[c],
                   row[c + 1], row[c + 2], row[c + 3]);
        } else {
            const float* rf = (const float*)row;
            int p0 = c * 4;
            o.x = hh_exact_px<4>(rf, p0);
            o.y = hh_exact_px<4>(rf, p0 + 1);
            o.z = hh_exact_px<4>(rf, p0 + 2);
            o.w = hh_exact_px<4>(rf, p0 + 3);
        }
        dst[(size_t)(y0 + r) * WV + c] = o;
    }
}

// ───────── Kernel C: level 5 (R=16, single level) for both chains + combine ─────────
__global__ void __launch_bounds__(640)
final5(const float4* __restrict__ lowHq, const float4* __restrict__ lowLq,
       const float4* __restrict__ hq, float4* __restrict__ out) {
    __shared__ float4 s[TH * WV];  // 40 KB static
    const int c = threadIdx.x, ty = threadIdx.y;
    const int y0 = blockIdx.x * TH;
    const int z = blockIdx.y;
    const float4* sH = lowHq + (size_t)z * NPV;
    const float4* sL = lowLq + (size_t)z * NPV;
    const float4* hp = hq + (size_t)z * NPV;
    float4* op = out + (size_t)z * NPV;

    // hq chain: vertical R=16 then horizontal R=16 -> acc regs
    #pragma unroll
    for (int r = ty; r < TH; r += 2) {
        int y = y0 + r;
        int ym = iclamp(y - 16, 0, Hd - 1), yp = iclamp(y + 16, 0, Hd - 1);
        s[r * WV + c] = vmix(sH[(size_t)ym * WV + c], sH[(size_t)y * WV + c],
                             sH[(size_t)yp * WV + c]);
    }
    __syncthreads();
    float4 acc[4];
    int k = 0;
    #pragma unroll
    for (int r = ty; r < TH; r += 2) {
        const float4* row = s + r * WV;
        float4 xm = (c >= 4) ? row[c - 4] : splat4(row[0].x);
        float4 xp = (c <= WV - 5) ? row[c + 4] : splat4(row[WV - 1].w);
        acc[k++] = vmix(xm, row[c], xp);
    }
    __syncthreads();
    // lq chain + combine
    #pragma unroll
    for (int r = ty; r < TH; r += 2) {
        int y = y0 + r;
        int ym = iclamp(y - 16, 0, Hd - 1), yp = iclamp(y + 16, 0, Hd - 1);
        s[r * WV + c] = vmix(sL[(size_t)ym * WV + c], sL[(size_t)y * WV + c],
                             sL[(size_t)yp * WV + c]);
    }
    __syncthreads();
    k = 0;
    #pragma unroll
    for (int r = ty; r < TH; r += 2) {
        const float4* row = s + r * WV;
        float4 xm = (c >= 4) ? row[c - 4] : splat4(row[0].x);
        float4 xp = (c <= WV - 5) ? row[c + 4] : splat4(row[WV - 1].w);
        float4 lo = vmix(xm, row[c], xp);
        float4 h = hp[(size_t)(y0 + r) * WV + c];
        float4 a = acc[k++];
        float4 o;
        o.x = fminf(fmaxf(h.x - a.x + lo.x, -1.0f), 1.0f);
        o.y = fminf(fmaxf(h.y - a.y + lo.y, -1.0f), 1.0f);
        o.z = fminf(fmaxf(h.z - a.z + lo.z, -1.0f), 1.0f);
        o.w = fminf(fmaxf(h.w - a.w + lo.w, -1.0f), 1.0f);
        op[(size_t)(y0 + r) * WV + c] = o;
    }
}

extern "C" void kernel_launch(void* const* d_in, const int* in_sizes, int n_in,
                              void* d_out, int out_size) {
    const float4* hq = (const float4*)d_in[0];
    const float4* lq = (const float4*)d_in[1];
    float4* out = (float4*)d_out;

    float4 *A, *B;
    cudaGetSymbolAddress((void**)&A, g_bufA);
    cudaGetSymbolAddress((void**)&B, g_bufB);

    dim3 blk(WV, 2);                      // 640 threads
    dim3 g2(NB, 2 * PLANES);              // (90, 96)
    dim3 g1(NB, PLANES);                  // (90, 48)

    levelAB<<<g2, blk>>>(hq, lq, A, A + NV4);            // inputs -> low2
    levelCD<<<g2, blk>>>(A, A + NV4, B, B + NV4);        // low2 -> low4
    final5 <<<g1, blk>>>(B, B + NV4, hq, out);           // low4 -> low5 + combine
}

// round 6
// speedup vs baseline: 2.4253x; 1.1855x over previous
#include <cuda_runtime.h>

#define Wd 1280
#define WV 320                 // float4 per row
#define Hd 720
#define NPV (Hd * WV)          // float4 per plane
#define PLANES 48
#define NV4 (PLANES * NPV)     // float4 per tensor

// Ping-pong scratch: [hq chain | lq chain]
__device__ float4 g_bufA[2 * NV4];
__device__ float4 g_bufB[2 * NV4];

__device__ __forceinline__ int iclamp(int v, int lo, int hi) {
    return v < lo ? lo : (v > hi ? hi : v);
}
__device__ __forceinline__ float4 splat4(float v) { return make_float4(v, v, v, v); }

// 0.25*(a+d) + 0.5*b
__device__ __forceinline__ float4 vmix(float4 a, float4 b, float4 d) {
    float4 o;
    o.x = fmaf(0.25f, a.x + d.x, 0.5f * b.x);
    o.y = fmaf(0.25f, a.y + d.y, 0.5f * b.y);
    o.z = fmaf(0.25f, a.z + d.z, 0.5f * b.z);
    o.w = fmaf(0.25f, a.w + d.w, 0.5f * b.w);
    return o;
}

// Fused two-level tap: [1,2,3,4,3,2,1]/16
__device__ __forceinline__ float t7(float a0, float a1, float a2, float a3,
                                    float a4, float a5, float a6) {
    return fmaf(0.25f, a3, fmaf(0.1875f, a2 + a4,
           fmaf(0.125f, a1 + a5, 0.0625f * (a0 + a6))));
}
__device__ __forceinline__ float4 f7(float4 a0, float4 a1, float4 a2, float4 a3,
                                     float4 a4, float4 a5, float4 a6) {
    float4 o;
    o.x = t7(a0.x, a1.x, a2.x, a3.x, a4.x, a5.x, a6.x);
    o.y = t7(a0.y, a1.y, a2.y, a3.y, a4.y, a5.y, a6.y);
    o.z = t7(a0.z, a1.z, a2.z, a3.z, a4.z, a5.z, a6.z);
    o.w = t7(a0.w, a1.w, a2.w, a3.w, a4.w, a5.w, a6.w);
    return o;
}

// Exact per-level vertical for border rows: V_{2R}(V_R(src)) with row clamps.
template <int RS>
__device__ __forceinline__ float4 v1tap(const float4* __restrict__ src, int q, int c) {
    q = iclamp(q, 0, Hd - 1);
    int ym = iclamp(q - RS, 0, Hd - 1), yp = iclamp(q + RS, 0, Hd - 1);
    return vmix(src[(size_t)ym * WV + c], src[(size_t)q * WV + c],
                src[(size_t)yp * WV + c]);
}
template <int RS>
__device__ __forceinline__ float4 vv_exact(const float4* __restrict__ src, int y, int c) {
    return vmix(v1tap<RS>(src, y - 2 * RS, c), v1tap<RS>(src, y, c),
                v1tap<RS>(src, y + 2 * RS, c));
}

// Exact per-level horizontal (border pixels), scalar, full-width row (AB).
template <int RS>
__device__ __forceinline__ float hh_lh(const float* row, int q) {
    q = iclamp(q, 0, Wd - 1);
    return fmaf(0.25f, row[iclamp(q - RS, 0, Wd - 1)] + row[iclamp(q + RS, 0, Wd - 1)],
                0.5f * row[q]);
}
template <int RS>
__device__ __forceinline__ float hh_exact_px(const float* row, int p) {
    return fmaf(0.25f, hh_lh<RS>(row, iclamp(p - 2 * RS, 0, Wd - 1)) +
                        hh_lh<RS>(row, iclamp(p + 2 * RS, 0, Wd - 1)),
                0.5f * hh_lh<RS>(row, p));
}

// Exact horizontal for CD on a tile-local row: rf indexed by (global px + off).
__device__ __forceinline__ float hh_lh4o(const float* rf, int q, int off) {
    q = iclamp(q, 0, Wd - 1);
    return fmaf(0.25f, rf[iclamp(q - 4, 0, Wd - 1) + off] +
                        rf[iclamp(q + 4, 0, Wd - 1) + off],
                0.5f * rf[q + off]);
}
__device__ __forceinline__ float hh_ex4(const float* rf, int p, int off) {
    return fmaf(0.25f, hh_lh4o(rf, iclamp(p - 8, 0, Wd - 1), off) +
                        hh_lh4o(rf, iclamp(p + 8, 0, Wd - 1), off),
                0.5f * hh_lh4o(rf, p, off));
}

// ───── Kernel A: levels 1+2 fused, sliding vertical window (1.75 LDG/out) ─────
#define TH_A 8
#define NB_A (Hd / TH_A)   // 90
__global__ void __launch_bounds__(320)
levelAB(const float4* __restrict__ srcHq, const float4* __restrict__ srcLq,
        float4* __restrict__ dstHq, float4* __restrict__ dstLq) {
    __shared__ float4 s[TH_A * WV];  // 40 KB static
    const int c = threadIdx.x;
    const int y0 = blockIdx.x * TH_A;
    const int z = blockIdx.y;
    const float4* src;
    float4* dst;
    if (z < PLANES) { src = srcHq + (size_t)z * NPV; dst = dstHq + (size_t)z * NPV; }
    else { src = srcLq + (size_t)(z - PLANES) * NPV; dst = dstLq + (size_t)(z - PLANES) * NPV; }

    if ((y0 >= 3) && (y0 + TH_A - 1 + 3 < Hd)) {
        const float4* p = src + (size_t)(y0 - 3) * WV + c;
        float4 w[7];
        #pragma unroll
        for (int i = 0; i < 7; i++) w[i] = __ldg(p + (size_t)i * WV);
        #pragma unroll
        for (int r = 0; r < TH_A; r++) {
            s[r * WV + c] = f7(w[r % 7], w[(r + 1) % 7], w[(r + 2) % 7], w[(r + 3) % 7],
                               w[(r + 4) % 7], w[(r + 5) % 7], w[(r + 6) % 7]);
            if (r < TH_A - 1) w[r % 7] = __ldg(p + (size_t)(7 + r) * WV);
        }
    } else {
        #pragma unroll
        for (int r = 0; r < TH_A; r++) s[r * WV + c] = vv_exact<1>(src, y0 + r, c);
    }
    __syncthreads();
    #pragma unroll
    for (int r = 0; r < TH_A; r++) {
        const float4* row = s + r * WV;
        float4 o;
        if (c >= 1 && c <= WV - 2) {
            float4 L = row[c - 1], C = row[c], R = row[c + 1];
            o.x = t7(L.y, L.z, L.w, C.x, C.y, C.z, C.w);
            o.y = t7(L.z, L.w, C.x, C.y, C.z, C.w, R.x);
            o.z = t7(L.w, C.x, C.y, C.z, C.w, R.x, R.y);
            o.w = t7(C.x, C.y, C.z, C.w, R.x, R.y, R.z);
        } else {
            const float* rf = (const float*)row;
            int p0 = c * 4;
            o.x = hh_exact_px<1>(rf, p0);
            o.y = hh_exact_px<1>(rf, p0 + 1);
            o.z = hh_exact_px<1>(rf, p0 + 2);
            o.w = hh_exact_px<1>(rf, p0 + 3);
        }
        dst[(size_t)(y0 + r) * WV + c] = o;
    }
}

// ───── Kernel B: levels 3+4 fused, residue-chain sliding vertical (2 LDG/out) ─────
// Band 24 rows, x-tiles of 160 output float4 (+3 halo each side -> 166 buffer cols).
#define TH_B 24
#define NB_B (Hd / TH_B)   // 30
#define TW_B 160
#define WT_B 166
__global__ void __launch_bounds__(672)
levelCD(const float4* __restrict__ srcHq, const float4* __restrict__ srcLq,
        float4* __restrict__ dstHq, float4* __restrict__ dstLq) {
    extern __shared__ float4 s[];  // [TH_B][WT_B] = 63744 B
    const int c = threadIdx.x;      // 0..167 (166..167 idle)
    const int rho = threadIdx.y;    // residue 0..3
    const int tx0 = blockIdx.x * TW_B;
    const int y0 = blockIdx.y * TH_B;
    const int z = blockIdx.z;
    const float4* src;
    float4* dst;
    if (z < PLANES) { src = srcHq + (size_t)z * NPV; dst = dstHq + (size_t)z * NPV; }
    else { src = srcLq + (size_t)(z - PLANES) * NPV; dst = dstLq + (size_t)(z - PLANES) * NPV; }

    if (c < WT_B) {
        const int jv = tx0 - 3 + c;
        const int gx = iclamp(jv, 0, WV - 1);
        // interior iff rows y0+rho-12 .. y0+rho+20+12 all in [0, Hd)
        if ((y0 >= 12) && (y0 + 3 + 32 < Hd)) {
            const float4* p = src + (size_t)(y0 + rho - 12) * WV + gx;
            float4 w[7];
            #pragma unroll
            for (int i = 0; i < 7; i++) w[i] = __ldg(p + (size_t)(4 * i) * WV);
            #pragma unroll
            for (int k = 0; k < 6; k++) {
                s[(rho + 4 * k) * WT_B + c] =
                    f7(w[k % 7], w[(k + 1) % 7], w[(k + 2) % 7], w[(k + 3) % 7],
                       w[(k + 4) % 7], w[(k + 5) % 7], w[(k + 6) % 7]);
                if (k < 5) w[k % 7] = __ldg(p + (size_t)(4 * (7 + k)) * WV);
            }
        } else {
            #pragma unroll
            for (int k = 0; k < 6; k++)
                s[(rho + 4 * k) * WT_B + c] = vv_exact<4>(src, y0 + rho + 4 * k, gx);
        }
    }
    __syncthreads();
    // horizontal: output cols are buffer cols 3..162
    if (c >= 3 && c <= 162) {
        const int j = tx0 + c - 3;
        #pragma unroll
        for (int k = 0; k < 6; k++) {
            const int rr = rho + 4 * k;
            const float4* row = s + rr * WT_B;
            float4 o;
            if (j >= 3 && j <= WV - 4) {
                o = f7(row[c - 3], row[c - 2], row[c - 1], row[c],
                       row[c + 1], row[c + 2], row[c + 3]);
            } else {
                const float* rf = (const float*)row;
                const int off = 12 - tx0 * 4;
                const int p0 = j * 4;
                o.x = hh_ex4(rf, p0, off);
                o.y = hh_ex4(rf, p0 + 1, off);
                o.z = hh_ex4(rf, p0 + 2, off);
                o.w = hh_ex4(rf, p0 + 3, off);
            }
            dst[(size_t)(y0 + rr) * WV + j] = o;
        }
    }
}

// ───── Kernel C: level 5 (R=16) for both chains + combine ─────
#define TH_C 8
__global__ void __launch_bounds__(640)
final5(const float4* __restrict__ lowHq, const float4* __restrict__ lowLq,
       const float4* __restrict__ hq, float4* __restrict__ out) {
    __shared__ float4 s[TH_C * WV];  // 40 KB static
    const int c = threadIdx.x, ty = threadIdx.y;
    const int y0 = blockIdx.x * TH_C;
    const int z = blockIdx.y;
    const float4* sH = lowHq + (size_t)z * NPV;
    const float4* sL = lowLq + (size_t)z * NPV;
    const float4* hp = hq + (size_t)z * NPV;
    float4* op = out + (size_t)z * NPV;

    #pragma unroll
    for (int r = ty; r < TH_C; r += 2) {
        int y = y0 + r;
        int ym = iclamp(y - 16, 0, Hd - 1), yp = iclamp(y + 16, 0, Hd - 1);
        s[r * WV + c] = vmix(sH[(size_t)ym * WV + c], sH[(size_t)y * WV + c],
                             sH[(size_t)yp * WV + c]);
    }
    __syncthreads();
    float4 acc[4];
    int k = 0;
    #pragma unroll
    for (int r = ty; r < TH_C; r += 2) {
        const float4* row = s + r * WV;
        float4 xm = (c >= 4) ? row[c - 4] : splat4(row[0].x);
        float4 xp = (c <= WV - 5) ? row[c + 4] : splat4(row[WV - 1].w);
        acc[k++] = vmix(xm, row[c], xp);
    }
    __syncthreads();
    #pragma unroll
    for (int r = ty; r < TH_C; r += 2) {
        int y = y0 + r;
        int ym = iclamp(y - 16, 0, Hd - 1), yp = iclamp(y + 16, 0, Hd - 1);
        s[r * WV + c] = vmix(sL[(size_t)ym * WV + c], sL[(size_t)y * WV + c],
                             sL[(size_t)yp * WV + c]);
    }
    __syncthreads();
    k = 0;
    #pragma unroll
    for (int r = ty; r < TH_C; r += 2) {
        const float4* row = s + r * WV;
        float4 xm = (c >= 4) ? row[c - 4] : splat4(row[0].x);
        float4 xp = (c <= WV - 5) ? row[c + 4] : splat4(row[WV - 1].w);
        float4 lo = vmix(xm, row[c], xp);
        float4 h = hp[(size_t)(y0 + r) * WV + c];
        float4 a = acc[k++];
        float4 o;
        o.x = fminf(fmaxf(h.x - a.x + lo.x, -1.0f), 1.0f);
        o.y = fminf(fmaxf(h.y - a.y + lo.y, -1.0f), 1.0f);
        o.z = fminf(fmaxf(h.z - a.z + lo.z, -1.0f), 1.0f);
        o.w = fminf(fmaxf(h.w - a.w + lo.w, -1.0f), 1.0f);
        op[(size_t)(y0 + r) * WV + c] = o;
    }
}

extern "C" void kernel_launch(void* const* d_in, const int* in_sizes, int n_in,
                              void* d_out, int out_size) {
    const float4* hq = (const float4*)d_in[0];
    const float4* lq = (const float4*)d_in[1];
    float4* out = (float4*)d_out;

    float4 *A, *B;
    cudaGetSymbolAddress((void**)&A, g_bufA);
    cudaGetSymbolAddress((void**)&B, g_bufB);

    const int smemB = TH_B * WT_B * sizeof(float4);  // 63744
    cudaFuncSetAttribute(levelCD, cudaFuncAttributeMaxDynamicSharedMemorySize, smemB);

    // levels 1+2: inputs -> A (low2, both chains)
    levelAB<<<dim3(NB_A, 2 * PLANES), dim3(320, 1)>>>(hq, lq, A, A + NV4);
    // levels 3+4: A -> B (low4)
    levelCD<<<dim3(WV / TW_B, NB_B, 2 * PLANES), dim3(168, 4), smemB>>>(
        A, A + NV4, B, B + NV4);
    // level 5 + combine
    final5<<<dim3(Hd / TH_C, PLANES), dim3(WV, 2)>>>(B, B + NV4, hq, out);
}

// round 7
// speedup vs baseline: 2.6545x; 1.0945x over previous
#include <cuda_runtime.h>
#include <cuda_fp16.h>

#define Wd 1280
#define WV 320                 // float4 per row
#define WH2 (WV * 2)           // half2 per row (640)
#define Hd 720
#define NPV (Hd * WV)          // float4 per plane
#define NPH2 (Hd * WH2)        // half2 per plane
#define PLANES 48
#define NV4 (PLANES * NPV)     // float4 per tensor
#define NH2 (PLANES * NPH2)    // half2 per tensor

// fp16 scratch: [hq chain | lq chain]
__device__ __half2 g_bufA[2 * NH2];
__device__ __half2 g_bufB[2 * NH2];

__device__ __forceinline__ int iclamp(int v, int lo, int hi) {
    return v < lo ? lo : (v > hi ? hi : v);
}
__device__ __forceinline__ float4 splat4(float v) { return make_float4(v, v, v, v); }

// load/store 4 px as fp16 (single 8-byte access)
__device__ __forceinline__ float4 ldh4(const __half2* p) {
    uint2 u = *(const uint2*)p;
    __half2 a = *(__half2*)&u.x, b = *(__half2*)&u.y;
    float2 fa = __half22float2(a), fb = __half22float2(b);
    return make_float4(fa.x, fa.y, fb.x, fb.y);
}
__device__ __forceinline__ void sth4(__half2* p, float4 v) {
    __half2 a = __floats2half2_rn(v.x, v.y), b = __floats2half2_rn(v.z, v.w);
    uint2 u;
    u.x = *(unsigned*)&a; u.y = *(unsigned*)&b;
    *(uint2*)p = u;
}

// 0.25*(a+d) + 0.5*b
__device__ __forceinline__ float4 vmix(float4 a, float4 b, float4 d) {
    float4 o;
    o.x = fmaf(0.25f, a.x + d.x, 0.5f * b.x);
    o.y = fmaf(0.25f, a.y + d.y, 0.5f * b.y);
    o.z = fmaf(0.25f, a.z + d.z, 0.5f * b.z);
    o.w = fmaf(0.25f, a.w + d.w, 0.5f * b.w);
    return o;
}

// Fused two-level tap: [1,2,3,4,3,2,1]/16
__device__ __forceinline__ float t7(float a0, float a1, float a2, float a3,
                                    float a4, float a5, float a6) {
    return fmaf(0.25f, a3, fmaf(0.1875f, a2 + a4,
           fmaf(0.125f, a1 + a5, 0.0625f * (a0 + a6))));
}
__device__ __forceinline__ float4 f7(float4 a0, float4 a1, float4 a2, float4 a3,
                                     float4 a4, float4 a5, float4 a6) {
    float4 o;
    o.x = t7(a0.x, a1.x, a2.x, a3.x, a4.x, a5.x, a6.x);
    o.y = t7(a0.y, a1.y, a2.y, a3.y, a4.y, a5.y, a6.y);
    o.z = t7(a0.z, a1.z, a2.z, a3.z, a4.z, a5.z, a6.z);
    o.w = t7(a0.w, a1.w, a2.w, a3.w, a4.w, a5.w, a6.w);
    return o;
}

// Exact border vertical, fp32 source (levels 1+2)
template <int RS>
__device__ __forceinline__ float4 v1tap(const float4* __restrict__ src, int q, int c) {
    q = iclamp(q, 0, Hd - 1);
    int ym = iclamp(q - RS, 0, Hd - 1), yp = iclamp(q + RS, 0, Hd - 1);
    return vmix(src[(size_t)ym * WV + c], src[(size_t)q * WV + c],
                src[(size_t)yp * WV + c]);
}
template <int RS>
__device__ __forceinline__ float4 vv_exact(const float4* __restrict__ src, int y, int c) {
    return vmix(v1tap<RS>(src, y - 2 * RS, c), v1tap<RS>(src, y, c),
                v1tap<RS>(src, y + 2 * RS, c));
}

// Exact border vertical, fp16 source (levels 3+4), c2 = 2*col in half2 units
__device__ __forceinline__ float4 v1tap_h4(const __half2* __restrict__ src, int q, int c2) {
    q = iclamp(q, 0, Hd - 1);
    int ym = iclamp(q - 4, 0, Hd - 1), yp = iclamp(q + 4, 0, Hd - 1);
    return vmix(ldh4(src + (size_t)ym * WH2 + c2), ldh4(src + (size_t)q * WH2 + c2),
                ldh4(src + (size_t)yp * WH2 + c2));
}
__device__ __forceinline__ float4 vv_exact_h4(const __half2* __restrict__ src, int y, int c2) {
    return vmix(v1tap_h4(src, y - 8, c2), v1tap_h4(src, y, c2), v1tap_h4(src, y + 8, c2));
}

// Exact border horizontal (full-width smem row, AB)
template <int RS>
__device__ __forceinline__ float hh_lh(const float* row, int q) {
    q = iclamp(q, 0, Wd - 1);
    return fmaf(0.25f, row[iclamp(q - RS, 0, Wd - 1)] + row[iclamp(q + RS, 0, Wd - 1)],
                0.5f * row[q]);
}
template <int RS>
__device__ __forceinline__ float hh_exact_px(const float* row, int p) {
    return fmaf(0.25f, hh_lh<RS>(row, iclamp(p - 2 * RS, 0, Wd - 1)) +
                        hh_lh<RS>(row, iclamp(p + 2 * RS, 0, Wd - 1)),
                0.5f * hh_lh<RS>(row, p));
}

// Exact border horizontal for CD tile rows (rf indexed by global px + off)
__device__ __forceinline__ float hh_lh4o(const float* rf, int q, int off) {
    q = iclamp(q, 0, Wd - 1);
    return fmaf(0.25f, rf[iclamp(q - 4, 0, Wd - 1) + off] +
                        rf[iclamp(q + 4, 0, Wd - 1) + off],
                0.5f * rf[q + off]);
}
__device__ __forceinline__ float hh_ex4(const float* rf, int p, int off) {
    return fmaf(0.25f, hh_lh4o(rf, iclamp(p - 8, 0, Wd - 1), off) +
                        hh_lh4o(rf, iclamp(p + 8, 0, Wd - 1), off),
                0.5f * hh_lh4o(rf, p, off));
}

// ───── Kernel A: levels 1+2 fused, sliding vertical window, fp16 out ─────
#define TH_A 8
#define NB_A (Hd / TH_A)   // 90
__global__ void __launch_bounds__(320)
levelAB(const float4* __restrict__ srcHq, const float4* __restrict__ srcLq,
        __half2* __restrict__ dstHq, __half2* __restrict__ dstLq) {
    __shared__ float4 s[TH_A * WV];  // 40 KB static, fp32
    const int c = threadIdx.x;
    const int y0 = blockIdx.x * TH_A;
    const int z = blockIdx.y;
    const float4* src;
    __half2* dst;
    if (z < PLANES) { src = srcHq + (size_t)z * NPV; dst = dstHq + (size_t)z * NPH2; }
    else { src = srcLq + (size_t)(z - PLANES) * NPV; dst = dstLq + (size_t)(z - PLANES) * NPH2; }

    if ((y0 >= 3) && (y0 + TH_A - 1 + 3 < Hd)) {
        const float4* p = src + (size_t)(y0 - 3) * WV + c;
        float4 w[7];
        #pragma unroll
        for (int i = 0; i < 7; i++) w[i] = __ldg(p + (size_t)i * WV);
        #pragma unroll
        for (int r = 0; r < TH_A; r++) {
            s[r * WV + c] = f7(w[r % 7], w[(r + 1) % 7], w[(r + 2) % 7], w[(r + 3) % 7],
                               w[(r + 4) % 7], w[(r + 5) % 7], w[(r + 6) % 7]);
            if (r < TH_A - 1) w[r % 7] = __ldg(p + (size_t)(7 + r) * WV);
        }
    } else {
        #pragma unroll
        for (int r = 0; r < TH_A; r++) s[r * WV + c] = vv_exact<1>(src, y0 + r, c);
    }
    __syncthreads();
    #pragma unroll
    for (int r = 0; r < TH_A; r++) {
        const float4* row = s + r * WV;
        float4 o;
        if (c >= 1 && c <= WV - 2) {
            float4 L = row[c - 1], C = row[c], R = row[c + 1];
            o.x = t7(L.y, L.z, L.w, C.x, C.y, C.z, C.w);
            o.y = t7(L.z, L.w, C.x, C.y, C.z, C.w, R.x);
            o.z = t7(L.w, C.x, C.y, C.z, C.w, R.x, R.y);
            o.w = t7(C.x, C.y, C.z, C.w, R.x, R.y, R.z);
        } else {
            const float* rf = (const float*)row;
            int p0 = c * 4;
            o.x = hh_exact_px<1>(rf, p0);
            o.y = hh_exact_px<1>(rf, p0 + 1);
            o.z = hh_exact_px<1>(rf, p0 + 2);
            o.w = hh_exact_px<1>(rf, p0 + 3);
        }
        sth4(dst + (size_t)(y0 + r) * WH2 + 2 * c, o);
    }
}

// ───── Kernel B: levels 3+4 fused, residue-chain sliding vertical, fp16 in/out ─────
#define TH_B 24
#define NB_B (Hd / TH_B)   // 30
#define TW_B 160
#define WT_B 166
__global__ void __launch_bounds__(672)
levelCD(const __half2* __restrict__ srcHq, const __half2* __restrict__ srcLq,
        __half2* __restrict__ dstHq, __half2* __restrict__ dstLq) {
    extern __shared__ float4 s[];  // [TH_B][WT_B] fp32 = 63744 B
    const int c = threadIdx.x;      // 0..167 (166..167 idle)
    const int rho = threadIdx.y;    // residue 0..3
    const int tx0 = blockIdx.x * TW_B;
    const int y0 = blockIdx.y * TH_B;
    const int z = blockIdx.z;
    const __half2* src;
    __half2* dst;
    if (z < PLANES) { src = srcHq + (size_t)z * NPH2; dst = dstHq + (size_t)z * NPH2; }
    else { src = srcLq + (size_t)(z - PLANES) * NPH2; dst = dstLq + (size_t)(z - PLANES) * NPH2; }

    if (c < WT_B) {
        const int jv = tx0 - 3 + c;
        const int c2 = 2 * iclamp(jv, 0, WV - 1);
        if ((y0 >= 12) && (y0 + 3 + 32 < Hd)) {
            const __half2* p = src + (size_t)(y0 + rho - 12) * WH2 + c2;
            float4 w[7];
            #pragma unroll
            for (int i = 0; i < 7; i++) w[i] = ldh4(p + (size_t)(4 * i) * WH2);
            #pragma unroll
            for (int k = 0; k < 6; k++) {
                s[(rho + 4 * k) * WT_B + c] =
                    f7(w[k % 7], w[(k + 1) % 7], w[(k + 2) % 7], w[(k + 3) % 7],
                       w[(k + 4) % 7], w[(k + 5) % 7], w[(k + 6) % 7]);
                if (k < 5) w[k % 7] = ldh4(p + (size_t)(4 * (7 + k)) * WH2);
            }
        } else {
            #pragma unroll
            for (int k = 0; k < 6; k++)
                s[(rho + 4 * k) * WT_B + c] = vv_exact_h4(src, y0 + rho + 4 * k, c2);
        }
    }
    __syncthreads();
    if (c >= 3 && c <= 162) {
        const int j = tx0 + c - 3;
        #pragma unroll
        for (int k = 0; k < 6; k++) {
            const int rr = rho + 4 * k;
            const float4* row = s + rr * WT_B;
            float4 o;
            if (j >= 3 && j <= WV - 4) {
                o = f7(row[c - 3], row[c - 2], row[c - 1], row[c],
                       row[c + 1], row[c + 2], row[c + 3]);
            } else {
                const float* rf = (const float*)row;
                const int off = 12 - tx0 * 4;
                const int p0 = j * 4;
                o.x = hh_ex4(rf, p0, off);
                o.y = hh_ex4(rf, p0 + 1, off);
                o.z = hh_ex4(rf, p0 + 2, off);
                o.w = hh_ex4(rf, p0 + 3, off);
            }
            sth4(dst + (size_t)(y0 + rr) * WH2 + 2 * j, o);
        }
    }
}

// ───── Kernel C: level 5 (R=16) both chains + combine, fp16 in, fp32 out ─────
#define TH_C 8
__global__ void __launch_bounds__(640)
final5(const __half2* __restrict__ lowHq, const __half2* __restrict__ lowLq,
       const float4* __restrict__ hq, float4* __restrict__ out) {
    __shared__ float4 s[TH_C * WV];  // 40 KB static
    const int c = threadIdx.x, ty = threadIdx.y;
    const int y0 = blockIdx.x * TH_C;
    const int z = blockIdx.y;
    const __half2* sH = lowHq + (size_t)z * NPH2;
    const __half2* sL = lowLq + (size_t)z * NPH2;
    const float4* hp = hq + (size_t)z * NPV;
    float4* op = out + (size_t)z * NPV;
    const int c2 = 2 * c;

    #pragma unroll
    for (int r = ty; r < TH_C; r += 2) {
        int y = y0 + r;
        int ym = iclamp(y - 16, 0, Hd - 1), yp = iclamp(y + 16, 0, Hd - 1);
        s[r * WV + c] = vmix(ldh4(sH + (size_t)ym * WH2 + c2),
                             ldh4(sH + (size_t)y * WH2 + c2),
                             ldh4(sH + (size_t)yp * WH2 + c2));
    }
    __syncthreads();
    float4 acc[4];
    int k = 0;
    #pragma unroll
    for (int r = ty; r < TH_C; r += 2) {
        const float4* row = s + r * WV;
        float4 xm = (c >= 4) ? row[c - 4] : splat4(row[0].x);
        float4 xp = (c <= WV - 5) ? row[c + 4] : splat4(row[WV - 1].w);
        acc[k++] = vmix(xm, row[c], xp);
    }
    __syncthreads();
    #pragma unroll
    for (int r = ty; r < TH_C; r += 2) {
        int y = y0 + r;
        int ym = iclamp(y - 16, 0, Hd - 1), yp = iclamp(y + 16, 0, Hd - 1);
        s[r * WV + c] = vmix(ldh4(sL + (size_t)ym * WH2 + c2),
                             ldh4(sL + (size_t)y * WH2 + c2),
                             ldh4(sL + (size_t)yp * WH2 + c2));
    }
    __syncthreads();
    k = 0;
    #pragma unroll
    for (int r = ty; r < TH_C; r += 2) {
        const float4* row = s + r * WV;
        float4 xm = (c >= 4) ? row[c - 4] : splat4(row[0].x);
        float4 xp = (c <= WV - 5) ? row[c + 4] : splat4(row[WV - 1].w);
        float4 lo = vmix(xm, row[c], xp);
        float4 h = hp[(size_t)(y0 + r) * WV + c];
        float4 a = acc[k++];
        float4 o;
        o.x = fminf(fmaxf(h.x - a.x + lo.x, -1.0f), 1.0f);
        o.y = fminf(fmaxf(h.y - a.y + lo.y, -1.0f), 1.0f);
        o.z = fminf(fmaxf(h.z - a.z + lo.z, -1.0f), 1.0f);
        o.w = fminf(fmaxf(h.w - a.w + lo.w, -1.0f), 1.0f);
        op[(size_t)(y0 + r) * WV + c] = o;
    }
}

extern "C" void kernel_launch(void* const* d_in, const int* in_sizes, int n_in,
                              void* d_out, int out_size) {
    const float4* hq = (const float4*)d_in[0];
    const float4* lq = (const float4*)d_in[1];
    float4* out = (float4*)d_out;

    __half2 *A, *B;
    cudaGetSymbolAddress((void**)&A, g_bufA);
    cudaGetSymbolAddress((void**)&B, g_bufB);

    const int smemB = TH_B * WT_B * sizeof(float4);  // 63744
    cudaFuncSetAttribute(levelCD, cudaFuncAttributeMaxDynamicSharedMemorySize, smemB);

    // levels 1+2: fp32 inputs -> A (low2, fp16, both chains)
    levelAB<<<dim3(NB_A, 2 * PLANES), dim3(320, 1)>>>(hq, lq, A, A + NH2);
    // levels 3+4: A -> B (low4, fp16)
    levelCD<<<dim3(WV / TW_B, NB_B, 2 * PLANES), dim3(168, 4), smemB>>>(
        A, A + NH2, B, B + NH2);
    // level 5 + combine: fp32 out
    final5<<<dim3(Hd / TH_C, PLANES), dim3(WV, 2)>>>(B, B + NH2, hq, out);
}

// round 9
// speedup vs baseline: 3.6860x; 1.3886x over previous
#include <cuda_runtime.h>
#include <cuda_fp16.h>

#define Wd 1280
#define WV 320                 // float4 per row
#define WH2 (WV * 2)           // half2 per row (640)
#define Hd 720
#define NPV (Hd * WV)          // float4 per plane
#define NPH2 (Hd * WH2)        // half2 per plane
#define PLANES 48
#define NH2 (PLANES * NPH2)    // half2 per tensor

// Single-chain fp16 scratch (d = hq - lq chain)
__device__ __half2 g_bufA[NH2];  // low2(d)
__device__ __half2 g_bufB[NH2];  // low4(d)

__device__ __forceinline__ int iclamp(int v, int lo, int hi) {
    return v < lo ? lo : (v > hi ? hi : v);
}
__device__ __forceinline__ float4 splat4(float v) { return make_float4(v, v, v, v); }

__device__ __forceinline__ float4 ldh4(const __half2* p) {
    uint2 u = *(const uint2*)p;
    __half2 a = *(__half2*)&u.x, b = *(__half2*)&u.y;
    float2 fa = __half22float2(a), fb = __half22float2(b);
    return make_float4(fa.x, fa.y, fb.x, fb.y);
}
__device__ __forceinline__ void sth4(__half2* p, float4 v) {
    __half2 a = __floats2half2_rn(v.x, v.y), b = __floats2half2_rn(v.z, v.w);
    uint2 u;
    u.x = *(unsigned*)&a; u.y = *(unsigned*)&b;
    *(uint2*)p = u;
}

__device__ __forceinline__ float4 fsub(float4 a, float4 b) {
    return make_float4(a.x - b.x, a.y - b.y, a.z - b.z, a.w - b.w);
}

// 0.25*(a+d) + 0.5*b
__device__ __forceinline__ float4 vmix(float4 a, float4 b, float4 d) {
    float4 o;
    o.x = fmaf(0.25f, a.x + d.x, 0.5f * b.x);
    o.y = fmaf(0.25f, a.y + d.y, 0.5f * b.y);
    o.z = fmaf(0.25f, a.z + d.z, 0.5f * b.z);
    o.w = fmaf(0.25f, a.w + d.w, 0.5f * b.w);
    return o;
}

// Fused two-level tap: [1,2,3,4,3,2,1]/16
__device__ __forceinline__ float t7(float a0, float a1, float a2, float a3,
                                    float a4, float a5, float a6) {
    return fmaf(0.25f, a3, fmaf(0.1875f, a2 + a4,
           fmaf(0.125f, a1 + a5, 0.0625f * (a0 + a6))));
}
__device__ __forceinline__ float4 f7(float4 a0, float4 a1, float4 a2, float4 a3,
                                     float4 a4, float4 a5, float4 a6) {
    float4 o;
    o.x = t7(a0.x, a1.x, a2.x, a3.x, a4.x, a5.x, a6.x);
    o.y = t7(a0.y, a1.y, a2.y, a3.y, a4.y, a5.y, a6.y);
    o.z = t7(a0.z, a1.z, a2.z, a3.z, a4.z, a5.z, a6.z);
    o.w = t7(a0.w, a1.w, a2.w, a3.w, a4.w, a5.w, a6.w);
    return o;
}

// ── Exact border vertical on the diff of two fp32 sources (levels 1+2) ──
__device__ __forceinline__ float4 dval(const float4* __restrict__ s1,
                                       const float4* __restrict__ s2, int q, int c) {
    return fsub(s1[(size_t)q * WV + c], s2[(size_t)q * WV + c]);
}
__device__ __forceinline__ float4 v1tap_d(const float4* __restrict__ s1,
                                          const float4* __restrict__ s2, int q, int c) {
    q = iclamp(q, 0, Hd - 1);
    int ym = iclamp(q - 1, 0, Hd - 1), yp = iclamp(q + 1, 0, Hd - 1);
    return vmix(dval(s1, s2, ym, c), dval(s1, s2, q, c), dval(s1, s2, yp, c));
}
__device__ __forceinline__ float4 vv_exact_d(const float4* __restrict__ s1,
                                             const float4* __restrict__ s2, int y, int c) {
    return vmix(v1tap_d(s1, s2, y - 2, c), v1tap_d(s1, s2, y, c),
                v1tap_d(s1, s2, y + 2, c));
}

// ── Exact border vertical, fp16 source, R=4 fused pair (levels 3+4) ──
__device__ __forceinline__ float4 v1tap_h4(const __half2* __restrict__ src, int q, int c2) {
    q = iclamp(q, 0, Hd - 1);
    int ym = iclamp(q - 4, 0, Hd - 1), yp = iclamp(q + 4, 0, Hd - 1);
    return vmix(ldh4(src + (size_t)ym * WH2 + c2), ldh4(src + (size_t)q * WH2 + c2),
                ldh4(src + (size_t)yp * WH2 + c2));
}
__device__ __forceinline__ float4 vv_exact_h4(const __half2* __restrict__ src, int y, int c2) {
    return vmix(v1tap_h4(src, y - 8, c2), v1tap_h4(src, y, c2), v1tap_h4(src, y + 8, c2));
}

// ── Exact border horizontal (full-width smem row, AB) ──
template <int RS>
__device__ __forceinline__ float hh_lh(const float* row, int q) {
    q = iclamp(q, 0, Wd - 1);
    return fmaf(0.25f, row[iclamp(q - RS, 0, Wd - 1)] + row[iclamp(q + RS, 0, Wd - 1)],
                0.5f * row[q]);
}
template <int RS>
__device__ __forceinline__ float hh_exact_px(const float* row, int p) {
    return fmaf(0.25f, hh_lh<RS>(row, iclamp(p - 2 * RS, 0, Wd - 1)) +
                        hh_lh<RS>(row, iclamp(p + 2 * RS, 0, Wd - 1)),
                0.5f * hh_lh<RS>(row, p));
}

// ── Exact border horizontal for CD tile rows (rf indexed by global px + off) ──
__device__ __forceinline__ float hh_lh4o(const float* rf, int q, int off) {
    q = iclamp(q, 0, Wd - 1);
    return fmaf(0.25f, rf[iclamp(q - 4, 0, Wd - 1) + off] +
                        rf[iclamp(q + 4, 0, Wd - 1) + off],
                0.5f * rf[q + off]);
}
__device__ __forceinline__ float hh_ex4(const float* rf, int p, int off) {
    return fmaf(0.25f, hh_lh4o(rf, iclamp(p - 8, 0, Wd - 1), off) +
                        hh_lh4o(rf, iclamp(p + 8, 0, Wd - 1), off),
                0.5f * hh_lh4o(rf, p, off));
}

// ───── Kernel A: d = hq - lq, levels 1+2 fused. 16-row band, 2 smem chunks.
// All __syncthreads at block-uniform points; interior test is block-uniform.
#define TH_A 16
#define NB_A (Hd / TH_A)   // 45
__global__ void __launch_bounds__(320)
levelAB(const float4* __restrict__ hq4, const float4* __restrict__ lq4,
        __half2* __restrict__ dstD) {
    __shared__ float4 s[8 * WV];  // 40 KB
    const int c = threadIdx.x;
    const int y0 = blockIdx.x * TH_A;
    const int z = blockIdx.y;
    const float4* s1 = hq4 + (size_t)z * NPV;
    const float4* s2 = lq4 + (size_t)z * NPV;
    __half2* dst = dstD + (size_t)z * NPH2;

    const bool interior = (y0 >= 3) && (y0 + TH_A - 1 + 3 < Hd);  // uniform per block
    const float4* p1 = s1 + (size_t)(y0 - 3) * WV + c;
    const float4* p2 = s2 + (size_t)(y0 - 3) * WV + c;
    float4 w[7];
    if (interior) {
        #pragma unroll
        for (int i = 0; i < 7; i++)
            w[i] = fsub(__ldg(p1 + (size_t)i * WV), __ldg(p2 + (size_t)i * WV));
    }

    #pragma unroll
    for (int ch = 0; ch < 2; ch++) {
        // phase 1: vertical -> smem (branch contains no syncs)
        if (interior) {
            #pragma unroll
            for (int r = 0; r < 8; r++) {
                const int rr = ch * 8 + r;
                s[r * WV + c] = f7(w[rr % 7], w[(rr + 1) % 7], w[(rr + 2) % 7],
                                   w[(rr + 3) % 7], w[(rr + 4) % 7], w[(rr + 5) % 7],
                                   w[(rr + 6) % 7]);
                if (rr < TH_A - 1)
                    w[rr % 7] = fsub(__ldg(p1 + (size_t)(7 + rr) * WV),
                                     __ldg(p2 + (size_t)(7 + rr) * WV));
            }
        } else {
            #pragma unroll
            for (int r = 0; r < 8; r++)
                s[r * WV + c] = vv_exact_d(s1, s2, y0 + ch * 8 + r, c);
        }
        __syncthreads();
        // phase 2: horizontal + fp16 store
        #pragma unroll
        for (int r = 0; r < 8; r++) {
            const float4* row = s + r * WV;
            float4 o;
            if (c >= 1 && c <= WV - 2) {
                float4 L = row[c - 1], C = row[c], R = row[c + 1];
                o.x = t7(L.y, L.z, L.w, C.x, C.y, C.z, C.w);
                o.y = t7(L.z, L.w, C.x, C.y, C.z, C.w, R.x);
                o.z = t7(L.w, C.x, C.y, C.z, C.w, R.x, R.y);
                o.w = t7(C.x, C.y, C.z, C.w, R.x, R.y, R.z);
            } else {
                const float* rf = (const float*)row;
                int p0 = c * 4;
                o.x = hh_exact_px<1>(rf, p0);
                o.y = hh_exact_px<1>(rf, p0 + 1);
                o.z = hh_exact_px<1>(rf, p0 + 2);
                o.w = hh_exact_px<1>(rf, p0 + 3);
            }
            sth4(dst + (size_t)(y0 + ch * 8 + r) * WH2 + 2 * c, o);
        }
        __syncthreads();
    }
}

// ───── Kernel B: levels 3+4 fused on d, residue chains, 48-row band, 2 chunks.
// Syncs at uniform points; thread-dependent guards contain no syncs.
#define TH_B 48
#define NB_B (Hd / TH_B)   // 15
#define TW_B 160
#define WT_B 166
__global__ void __launch_bounds__(672)
levelCD(const __half2* __restrict__ srcD, __half2* __restrict__ dstD) {
    extern __shared__ float4 s[];  // [24][WT_B] = 63744 B
    const int c = threadIdx.x;      // 0..167 (166..167 idle in vertical)
    const int rho = threadIdx.y;    // residue 0..3
    const int tx0 = blockIdx.x * TW_B;
    const int y0 = blockIdx.y * TH_B;
    const int z = blockIdx.z;
    const __half2* src = srcD + (size_t)z * NPH2;
    __half2* dst = dstD + (size_t)z * NPH2;

    const int jv = tx0 - 3 + c;
    const int c2 = 2 * iclamp(jv, 0, WV - 1);
    // interior iff rows y0+rho-12 .. y0+rho+44+12 all within [0, Hd)
    const bool interior = (y0 >= 12) && (y0 + 3 + 44 + 12 < Hd);  // uniform per block
    const __half2* p = src + (size_t)(y0 + rho - 12) * WH2 + c2;
    float4 w[7];
    if (interior && c < WT_B) {
        #pragma unroll
        for (int i = 0; i < 7; i++) w[i] = ldh4(p + (size_t)(4 * i) * WH2);
    }

    #pragma unroll
    for (int ch = 0; ch < 2; ch++) {
        // phase 1: vertical fused pair -> smem
        if (c < WT_B) {
            if (interior) {
                #pragma unroll
                for (int k = 0; k < 6; k++) {
                    const int kk = ch * 6 + k;
                    s[(rho + 4 * k) * WT_B + c] =
                        f7(w[kk % 7], w[(kk + 1) % 7], w[(kk + 2) % 7], w[(kk + 3) % 7],
                           w[(kk + 4) % 7], w[(kk + 5) % 7], w[(kk + 6) % 7]);
                    if (kk < 11) w[kk % 7] = ldh4(p + (size_t)(4 * (7 + kk)) * WH2);
                }
            } else {
                #pragma unroll
                for (int k = 0; k < 6; k++)
                    s[(rho + 4 * k) * WT_B + c] =
                        vv_exact_h4(src, y0 + ch * 24 + rho + 4 * k, c2);
            }
        }
        __syncthreads();
        // phase 2: horizontal fused pair + fp16 store
        if (c >= 3 && c <= 162) {
            const int j = tx0 + c - 3;
            #pragma unroll
            for (int k = 0; k < 6; k++) {
                const int rr = ch * 24 + rho + 4 * k;
                const float4* row = s + (rho + 4 * k) * WT_B;
                float4 o;
                if (j >= 3 && j <= WV - 4) {
                    o = f7(row[c - 3], row[c - 2], row[c - 1], row[c],
                           row[c + 1], row[c + 2], row[c + 3]);
                } else {
                    const float* rf = (const float*)row;
                    const int off = 12 - tx0 * 4;
                    const int p0 = j * 4;
                    o.x = hh_ex4(rf, p0, off);
                    o.y = hh_ex4(rf, p0 + 1, off);
                    o.z = hh_ex4(rf, p0 + 2, off);
                    o.w = hh_ex4(rf, p0 + 3, off);
                }
                sth4(dst + (size_t)(y0 + rr) * WH2 + 2 * j, o);
            }
        }
        __syncthreads();
    }
}

// ───── Kernel C: level 5 (R=16) on d + combine: out = clip(hq - low5d) ─────
#define TH_C 8
__global__ void __launch_bounds__(640)
final5(const __half2* __restrict__ lowD, const float4* __restrict__ hq4,
       float4* __restrict__ out) {
    __shared__ float4 s[TH_C * WV];  // 40 KB
    const int c = threadIdx.x, ty = threadIdx.y;
    const int y0 = blockIdx.x * TH_C;
    const int z = blockIdx.y;
    const __half2* sD = lowD + (size_t)z * NPH2;
    const float4* hp = hq4 + (size_t)z * NPV;
    float4* op = out + (size_t)z * NPV;
    const int c2 = 2 * c;

    #pragma unroll
    for (int r = ty; r < TH_C; r += 2) {
        int y = y0 + r;
        int ym = iclamp(y - 16, 0, Hd - 1), yp = iclamp(y + 16, 0, Hd - 1);
        s[r * WV + c] = vmix(ldh4(sD + (size_t)ym * WH2 + c2),
                             ldh4(sD + (size_t)y * WH2 + c2),
                             ldh4(sD + (size_t)yp * WH2 + c2));
    }
    __syncthreads();
    #pragma unroll
    for (int r = ty; r < TH_C; r += 2) {
        const float4* row = s + r * WV;
        float4 xm = (c >= 4) ? row[c - 4] : splat4(row[0].x);
        float4 xp = (c <= WV - 5) ? row[c + 4] : splat4(row[WV - 1].w);
        float4 lo = vmix(xm, row[c], xp);
        float4 h = hp[(size_t)(y0 + r) * WV + c];
        float4 o;
        o.x = fminf(fmaxf(h.x - lo.x, -1.0f), 1.0f);
        o.y = fminf(fmaxf(h.y - lo.y, -1.0f), 1.0f);
        o.z = fminf(fmaxf(h.z - lo.z, -1.0f), 1.0f);
        o.w = fminf(fmaxf(h.w - lo.w, -1.0f), 1.0f);
        op[(size_t)(y0 + r) * WV + c] = o;
    }
}

extern "C" void kernel_launch(void* const* d_in, const int* in_sizes, int n_in,
                              void* d_out, int out_size) {
    const float4* hq = (const float4*)d_in[0];
    const float4* lq = (const float4*)d_in[1];
    float4* out = (float4*)d_out;

    __half2 *A, *B;
    cudaGetSymbolAddress((void**)&A, g_bufA);
    cudaGetSymbolAddress((void**)&B, g_bufB);

    const int smemB = 24 * WT_B * sizeof(float4);  // 63744
    cudaFuncSetAttribute(levelCD, cudaFuncAttributeMaxDynamicSharedMemorySize, smemB);

    // levels 1+2 on d = hq - lq: fp32 inputs -> A (low2(d), fp16)
    levelAB<<<dim3(NB_A, PLANES), dim3(320, 1)>>>(hq, lq, A);
    // levels 3+4: A -> B (low4(d), fp16)
    levelCD<<<dim3(WV / TW_B, NB_B, PLANES), dim3(168, 4), smemB>>>(A, B);
    // level 5 + combine: out = clip(hq - low5(d))
    final5<<<dim3(Hd / TH_C, PLANES), dim3(WV, 2)>>>(B, hq, out);
}

// round 12
// speedup vs baseline: 3.8099x; 1.0336x over previous
#include <cuda_runtime.h>
#include <cuda_fp16.h>

#define Wd 1280
#define WV 320                 // float4 per row
#define WH2 (WV * 2)           // half2 per row (640)
#define Hd 720
#define NPV (Hd * WV)          // float4 per plane
#define NPH2 (Hd * WH2)        // half2 per plane
#define PLANES 48
#define NH2 (PLANES * NPH2)    // half2 per tensor

// Single-chain fp16 scratch (d = hq - lq chain)
__device__ __half2 g_bufA[NH2];  // low2(d)
__device__ __half2 g_bufB[NH2];  // low4(d)

__device__ __forceinline__ int iclamp(int v, int lo, int hi) {
    return v < lo ? lo : (v > hi ? hi : v);
}
__device__ __forceinline__ float4 splat4(float v) { return make_float4(v, v, v, v); }

__device__ __forceinline__ float4 ldh4(const __half2* p) {
    uint2 u = *(const uint2*)p;
    __half2 a = *(__half2*)&u.x, b = *(__half2*)&u.y;
    float2 fa = __half22float2(a), fb = __half22float2(b);
    return make_float4(fa.x, fa.y, fb.x, fb.y);
}
__device__ __forceinline__ void sth4(__half2* p, float4 v) {
    __half2 a = __floats2half2_rn(v.x, v.y), b = __floats2half2_rn(v.z, v.w);
    uint2 u;
    u.x = *(unsigned*)&a; u.y = *(unsigned*)&b;
    *(uint2*)p = u;
}

__device__ __forceinline__ float4 fsub(float4 a, float4 b) {
    return make_float4(a.x - b.x, a.y - b.y, a.z - b.z, a.w - b.w);
}

// 0.25*(a+d) + 0.5*b
__device__ __forceinline__ float4 vmix(float4 a, float4 b, float4 d) {
    float4 o;
    o.x = fmaf(0.25f, a.x + d.x, 0.5f * b.x);
    o.y = fmaf(0.25f, a.y + d.y, 0.5f * b.y);
    o.z = fmaf(0.25f, a.z + d.z, 0.5f * b.z);
    o.w = fmaf(0.25f, a.w + d.w, 0.5f * b.w);
    return o;
}

// Fused two-level tap: [1,2,3,4,3,2,1]/16
__device__ __forceinline__ float t7(float a0, float a1, float a2, float a3,
                                    float a4, float a5, float a6) {
    return fmaf(0.25f, a3, fmaf(0.1875f, a2 + a4,
           fmaf(0.125f, a1 + a5, 0.0625f * (a0 + a6))));
}
__device__ __forceinline__ float4 f7(float4 a0, float4 a1, float4 a2, float4 a3,
                                     float4 a4, float4 a5, float4 a6) {
    float4 o;
    o.x = t7(a0.x, a1.x, a2.x, a3.x, a4.x, a5.x, a6.x);
    o.y = t7(a0.y, a1.y, a2.y, a3.y, a4.y, a5.y, a6.y);
    o.z = t7(a0.z, a1.z, a2.z, a3.z, a4.z, a5.z, a6.z);
    o.w = t7(a0.w, a1.w, a2.w, a3.w, a4.w, a5.w, a6.w);
    return o;
}

// ── Exact border vertical on the diff of two fp32 sources (levels 1+2) ──
__device__ __forceinline__ float4 dval(const float4* __restrict__ s1,
                                       const float4* __restrict__ s2, int q, int c) {
    return fsub(s1[(size_t)q * WV + c], s2[(size_t)q * WV + c]);
}
__device__ __forceinline__ float4 v1tap_d(const float4* __restrict__ s1,
                                          const float4* __restrict__ s2, int q, int c) {
    q = iclamp(q, 0, Hd - 1);
    int ym = iclamp(q - 1, 0, Hd - 1), yp = iclamp(q + 1, 0, Hd - 1);
    return vmix(dval(s1, s2, ym, c), dval(s1, s2, q, c), dval(s1, s2, yp, c));
}
__device__ __forceinline__ float4 vv_exact_d(const float4* __restrict__ s1,
                                             const float4* __restrict__ s2, int y, int c) {
    return vmix(v1tap_d(s1, s2, y - 2, c), v1tap_d(s1, s2, y, c),
                v1tap_d(s1, s2, y + 2, c));
}

// ── Exact border vertical, fp16 source, R=4 fused pair (levels 3+4) ──
__device__ __forceinline__ float4 v1tap_h4(const __half2* __restrict__ src, int q, int c2) {
    q = iclamp(q, 0, Hd - 1);
    int ym = iclamp(q - 4, 0, Hd - 1), yp = iclamp(q + 4, 0, Hd - 1);
    return vmix(ldh4(src + (size_t)ym * WH2 + c2), ldh4(src + (size_t)q * WH2 + c2),
                ldh4(src + (size_t)yp * WH2 + c2));
}
__device__ __forceinline__ float4 vv_exact_h4(const __half2* __restrict__ src, int y, int c2) {
    return vmix(v1tap_h4(src, y - 8, c2), v1tap_h4(src, y, c2), v1tap_h4(src, y + 8, c2));
}

// ── Exact border horizontal (full-width fp32 smem row, AB) ──
template <int RS>
__device__ __forceinline__ float hh_lh(const float* row, int q) {
    q = iclamp(q, 0, Wd - 1);
    return fmaf(0.25f, row[iclamp(q - RS, 0, Wd - 1)] + row[iclamp(q + RS, 0, Wd - 1)],
                0.5f * row[q]);
}
template <int RS>
__device__ __forceinline__ float hh_exact_px(const float* row, int p) {
    return fmaf(0.25f, hh_lh<RS>(row, iclamp(p - 2 * RS, 0, Wd - 1)) +
                        hh_lh<RS>(row, iclamp(p + 2 * RS, 0, Wd - 1)),
                0.5f * hh_lh<RS>(row, p));
}

// ── Exact border horizontal for CD tile rows, fp16 smem row ──
__device__ __forceinline__ float hh_lh4h(const __half* rh, int q, int off) {
    q = iclamp(q, 0, Wd - 1);
    return fmaf(0.25f, __half2float(rh[iclamp(q - 4, 0, Wd - 1) + off]) +
                        __half2float(rh[iclamp(q + 4, 0, Wd - 1) + off]),
                0.5f * __half2float(rh[q + off]));
}
__device__ __forceinline__ float hh_ex4h(const __half* rh, int p, int off) {
    return fmaf(0.25f, hh_lh4h(rh, iclamp(p - 8, 0, Wd - 1), off) +
                        hh_lh4h(rh, iclamp(p + 8, 0, Wd - 1), off),
                0.5f * hh_lh4h(rh, p, off));
}

// ───── Kernel A (unchanged from R9): d = hq - lq, levels 1+2 fused, 16-row band ─────
#define TH_A 16
#define NB_A (Hd / TH_A)   // 45
__global__ void __launch_bounds__(320)
levelAB(const float4* __restrict__ hq4, const float4* __restrict__ lq4,
        __half2* __restrict__ dstD) {
    __shared__ float4 s[8 * WV];  // 40 KB
    const int c = threadIdx.x;
    const int y0 = blockIdx.x * TH_A;
    const int z = blockIdx.y;
    const float4* s1 = hq4 + (size_t)z * NPV;
    const float4* s2 = lq4 + (size_t)z * NPV;
    __half2* dst = dstD + (size_t)z * NPH2;

    const bool interior = (y0 >= 3) && (y0 + TH_A - 1 + 3 < Hd);
    const float4* p1 = s1 + (size_t)(y0 - 3) * WV + c;
    const float4* p2 = s2 + (size_t)(y0 - 3) * WV + c;
    float4 w[7];
    if (interior) {
        #pragma unroll
        for (int i = 0; i < 7; i++)
            w[i] = fsub(__ldg(p1 + (size_t)i * WV), __ldg(p2 + (size_t)i * WV));
    }

    #pragma unroll
    for (int ch = 0; ch < 2; ch++) {
        if (interior) {
            #pragma unroll
            for (int r = 0; r < 8; r++) {
                const int rr = ch * 8 + r;
                s[r * WV + c] = f7(w[rr % 7], w[(rr + 1) % 7], w[(rr + 2) % 7],
                                   w[(rr + 3) % 7], w[(rr + 4) % 7], w[(rr + 5) % 7],
                                   w[(rr + 6) % 7]);
                if (rr < TH_A - 1)
                    w[rr % 7] = fsub(__ldg(p1 + (size_t)(7 + rr) * WV),
                                     __ldg(p2 + (size_t)(7 + rr) * WV));
            }
        } else {
            #pragma unroll
            for (int r = 0; r < 8; r++)
                s[r * WV + c] = vv_exact_d(s1, s2, y0 + ch * 8 + r, c);
        }
        __syncthreads();
        #pragma unroll
        for (int r = 0; r < 8; r++) {
            const float4* row = s + r * WV;
            float4 o;
            if (c >= 1 && c <= WV - 2) {
                float4 L = row[c - 1], C = row[c], R = row[c + 1];
                o.x = t7(L.y, L.z, L.w, C.x, C.y, C.z, C.w);
                o.y = t7(L.z, L.w, C.x, C.y, C.z, C.w, R.x);
                o.z = t7(L.w, C.x, C.y, C.z, C.w, R.x, R.y);
                o.w = t7(C.x, C.y, C.z, C.w, R.x, R.y, R.z);
            } else {
                const float* rf = (const float*)row;
                int p0 = c * 4;
                o.x = hh_exact_px<1>(rf, p0);
                o.y = hh_exact_px<1>(rf, p0 + 1);
                o.z = hh_exact_px<1>(rf, p0 + 2);
                o.w = hh_exact_px<1>(rf, p0 + 3);
            }
            sth4(dst + (size_t)(y0 + ch * 8 + r) * WH2 + 2 * c, o);
        }
        __syncthreads();
    }
}

// ───── Kernel B: levels 3+4 fused on d, residue chains, fp16 smem (2 CTAs/SM) ─────
#define TH_B 48
#define NB_B (Hd / TH_B)   // 15
#define TW_B 160
#define WT_B 166
#define SWH (WT_B * 2)     // half2 per smem row (332)
__global__ void __launch_bounds__(672)
levelCD(const __half2* __restrict__ srcD, __half2* __restrict__ dstD) {
    extern __shared__ __half2 vb[];  // [24][SWH] fp16 = 31872 B
    const int c = threadIdx.x;      // 0..167 (166..167 idle in vertical)
    const int rho = threadIdx.y;    // residue 0..3
    const int tx0 = blockIdx.x * TW_B;
    const int y0 = blockIdx.y * TH_B;
    const int z = blockIdx.z;
    const __half2* src = srcD + (size_t)z * NPH2;
    __half2* dst = dstD + (size_t)z * NPH2;

    const int jv = tx0 - 3 + c;
    const int c2 = 2 * iclamp(jv, 0, WV - 1);
    const bool interior = (y0 >= 12) && (y0 + 3 + 44 + 12 < Hd);  // uniform
    const __half2* p = src + (size_t)(y0 + rho - 12) * WH2 + c2;
    float4 w[7];
    if (interior && c < WT_B) {
        #pragma unroll
        for (int i = 0; i < 7; i++) w[i] = ldh4(p + (size_t)(4 * i) * WH2);
    }

    #pragma unroll
    for (int ch = 0; ch < 2; ch++) {
        // phase 1: vertical fused pair -> fp16 smem
        if (c < WT_B) {
            if (interior) {
                #pragma unroll
                for (int k = 0; k < 6; k++) {
                    const int kk = ch * 6 + k;
                    sth4(&vb[(rho + 4 * k) * SWH + 2 * c],
                         f7(w[kk % 7], w[(kk + 1) % 7], w[(kk + 2) % 7], w[(kk + 3) % 7],
                            w[(kk + 4) % 7], w[(kk + 5) % 7], w[(kk + 6) % 7]));
                    if (kk < 11) w[kk % 7] = ldh4(p + (size_t)(4 * (7 + kk)) * WH2);
                }
            } else {
                #pragma unroll
                for (int k = 0; k < 6; k++)
                    sth4(&vb[(rho + 4 * k) * SWH + 2 * c],
                         vv_exact_h4(src, y0 + ch * 24 + rho + 4 * k, c2));
            }
        }
        __syncthreads();
        // phase 2: horizontal fused pair + fp16 store
        if (c >= 3 && c <= 162) {
            const int j = tx0 + c - 3;
            #pragma unroll
            for (int k = 0; k < 6; k++) {
                const int rr = ch * 24 + rho + 4 * k;
                const __half2* row = vb + (rho + 4 * k) * SWH;
                float4 o;
                if (j >= 3 && j <= WV - 4) {
                    o = f7(ldh4(row + 2 * (c - 3)), ldh4(row + 2 * (c - 2)),
                           ldh4(row + 2 * (c - 1)), ldh4(row + 2 * c),
                           ldh4(row + 2 * (c + 1)), ldh4(row + 2 * (c + 2)),
                           ldh4(row + 2 * (c + 3)));
                } else {
                    const __half* rh = (const __half*)row;
                    const int off = 12 - tx0 * 4;
                    const int p0 = j * 4;
                    o.x = hh_ex4h(rh, p0, off);
                    o.y = hh_ex4h(rh, p0 + 1, off);
                    o.z = hh_ex4h(rh, p0 + 2, off);
                    o.w = hh_ex4h(rh, p0 + 3, off);
                }
                sth4(dst + (size_t)(y0 + rr) * WH2 + 2 * j, o);
            }
        }
        __syncthreads();
    }
}

// ───── Kernel C: level 5 (R=16) on d + combine, 24-row bands (3 chunks of 8) ─────
#define TH_C 24
#define NB_C (Hd / TH_C)   // 30
__global__ void __launch_bounds__(640)
final5(const __half2* __restrict__ lowD, const float4* __restrict__ hq4,
       float4* __restrict__ out) {
    __shared__ float4 s[8 * WV];  // 40 KB
    const int c = threadIdx.x, ty = threadIdx.y;
    const int y0 = blockIdx.x * TH_C;
    const int z = blockIdx.y;
    const __half2* sD = lowD + (size_t)z * NPH2;
    const float4* hp = hq4 + (size_t)z * NPV;
    float4* op = out + (size_t)z * NPV;
    const int c2 = 2 * c;

    #pragma unroll
    for (int ch = 0; ch < 3; ch++) {
        const int yb = y0 + ch * 8;
        // phase 1: vertical R=16 -> smem (independent ldh4s batch for MLP)
        #pragma unroll
        for (int r = ty; r < 8; r += 2) {
            int y = yb + r;
            int ym = iclamp(y - 16, 0, Hd - 1), yp = iclamp(y + 16, 0, Hd - 1);
            s[r * WV + c] = vmix(ldh4(sD + (size_t)ym * WH2 + c2),
                                 ldh4(sD + (size_t)y * WH2 + c2),
                                 ldh4(sD + (size_t)yp * WH2 + c2));
        }
        __syncthreads();
        // phase 2: horizontal R=16 + combine + store
        #pragma unroll
        for (int r = ty; r < 8; r += 2) {
            const float4* row = s + r * WV;
            float4 xm = (c >= 4) ? row[c - 4] : splat4(row[0].x);
            float4 xp = (c <= WV - 5) ? row[c + 4] : splat4(row[WV - 1].w);
            float4 lo = vmix(xm, row[c], xp);
            float4 h = __ldg(hp + (size_t)(yb + r) * WV + c);
            float4 o;
            o.x = fminf(fmaxf(h.x - lo.x, -1.0f), 1.0f);
            o.y = fminf(fmaxf(h.y - lo.y, -1.0f), 1.0f);
            o.z = fminf(fmaxf(h.z - lo.z, -1.0f), 1.0f);
            o.w = fminf(fmaxf(h.w - lo.w, -1.0f), 1.0f);
            op[(size_t)(yb + r) * WV + c] = o;
        }
        __syncthreads();
    }
}

extern "C" void kernel_launch(void* const* d_in, const int* in_sizes, int n_in,
                              void* d_out, int out_size) {
    const float4* hq = (const float4*)d_in[0];
    const float4* lq = (const float4*)d_in[1];
    float4* out = (float4*)d_out;

    __half2 *A, *B;
    cudaGetSymbolAddress((void**)&A, g_bufA);
    cudaGetSymbolAddress((void**)&B, g_bufB);

    const int smemB = 24 * SWH * sizeof(__half2);  // 31872
    cudaFuncSetAttribute(levelCD, cudaFuncAttributeMaxDynamicSharedMemorySize, smemB);

    // levels 1+2 on d = hq - lq: fp32 inputs -> A (low2(d), fp16)
    levelAB<<<dim3(NB_A, PLANES), dim3(320, 1)>>>(hq, lq, A);
    // levels 3+4: A -> B (low4(d), fp16)
    levelCD<<<dim3(WV / TW_B, NB_B, PLANES), dim3(168, 4), smemB>>>(A, B);
    // level 5 + combine: out = clip(hq - low5(d))
    final5<<<dim3(NB_C, PLANES), dim3(WV, 2)>>>(B, hq, out);
}

// round 13
// speedup vs baseline: 4.3268x; 1.1357x over previous
#include <cuda_runtime.h>
#include <cuda_fp16.h>

#define Wd 1280
#define WV 320                 // float4 per row
#define WH2 (WV * 2)           // half2 per row (640)
#define Hd 720
#define NPV (Hd * WV)          // float4 per plane
#define NPH2 (Hd * WH2)        // half2 per plane
#define PLANES 48
#define NH2 (PLANES * NPH2)    // half2 per tensor

// Single-chain fp16 scratch (d = hq - lq chain)
__device__ __half2 g_bufA[NH2];  // low2(d)
__device__ __half2 g_bufB[NH2];  // low4(d)

__device__ __forceinline__ int iclamp(int v, int lo, int hi) {
    return v < lo ? lo : (v > hi ? hi : v);
}
__device__ __forceinline__ float4 splat4(float v) { return make_float4(v, v, v, v); }

__device__ __forceinline__ float4 ldh4(const __half2* p) {
    uint2 u = *(const uint2*)p;
    __half2 a = *(__half2*)&u.x, b = *(__half2*)&u.y;
    float2 fa = __half22float2(a), fb = __half22float2(b);
    return make_float4(fa.x, fa.y, fb.x, fb.y);
}
__device__ __forceinline__ void sth4(__half2* p, float4 v) {
    __half2 a = __floats2half2_rn(v.x, v.y), b = __floats2half2_rn(v.z, v.w);
    uint2 u;
    u.x = *(unsigned*)&a; u.y = *(unsigned*)&b;
    *(uint2*)p = u;
}
// packed fp16 quad in 2 regs
__device__ __forceinline__ uint2 pack4(float4 v) {
    __half2 a = __floats2half2_rn(v.x, v.y), b = __floats2half2_rn(v.z, v.w);
    uint2 u;
    u.x = *(unsigned*)&a; u.y = *(unsigned*)&b;
    return u;
}
__device__ __forceinline__ float4 unpack4(uint2 u) {
    __half2 a = *(__half2*)&u.x, b = *(__half2*)&u.y;
    float2 fa = __half22float2(a), fb = __half22float2(b);
    return make_float4(fa.x, fa.y, fb.x, fb.y);
}
__device__ __forceinline__ uint2 ldh4r(const __half2* p) { return *(const uint2*)p; }

__device__ __forceinline__ float4 fsub(float4 a, float4 b) {
    return make_float4(a.x - b.x, a.y - b.y, a.z - b.z, a.w - b.w);
}

// 0.25*(a+d) + 0.5*b
__device__ __forceinline__ float4 vmix(float4 a, float4 b, float4 d) {
    float4 o;
    o.x = fmaf(0.25f, a.x + d.x, 0.5f * b.x);
    o.y = fmaf(0.25f, a.y + d.y, 0.5f * b.y);
    o.z = fmaf(0.25f, a.z + d.z, 0.5f * b.z);
    o.w = fmaf(0.25f, a.w + d.w, 0.5f * b.w);
    return o;
}

// Fused two-level tap: [1,2,3,4,3,2,1]/16
__device__ __forceinline__ float t7(float a0, float a1, float a2, float a3,
                                    float a4, float a5, float a6) {
    return fmaf(0.25f, a3, fmaf(0.1875f, a2 + a4,
           fmaf(0.125f, a1 + a5, 0.0625f * (a0 + a6))));
}
__device__ __forceinline__ float4 f7(float4 a0, float4 a1, float4 a2, float4 a3,
                                     float4 a4, float4 a5, float4 a6) {
    float4 o;
    o.x = t7(a0.x, a1.x, a2.x, a3.x, a4.x, a5.x, a6.x);
    o.y = t7(a0.y, a1.y, a2.y, a3.y, a4.y, a5.y, a6.y);
    o.z = t7(a0.z, a1.z, a2.z, a3.z, a4.z, a5.z, a6.z);
    o.w = t7(a0.w, a1.w, a2.w, a3.w, a4.w, a5.w, a6.w);
    return o;
}

// ── Exact border vertical on the diff of two fp32 sources (levels 1+2) ──
__device__ __forceinline__ float4 dval(const float4* __restrict__ s1,
                                       const float4* __restrict__ s2, int q, int c) {
    return fsub(s1[(size_t)q * WV + c], s2[(size_t)q * WV + c]);
}
__device__ __forceinline__ float4 v1tap_d(const float4* __restrict__ s1,
                                          const float4* __restrict__ s2, int q, int c) {
    q = iclamp(q, 0, Hd - 1);
    int ym = iclamp(q - 1, 0, Hd - 1), yp = iclamp(q + 1, 0, Hd - 1);
    return vmix(dval(s1, s2, ym, c), dval(s1, s2, q, c), dval(s1, s2, yp, c));
}
__device__ __forceinline__ float4 vv_exact_d(const float4* __restrict__ s1,
                                             const float4* __restrict__ s2, int y, int c) {
    return vmix(v1tap_d(s1, s2, y - 2, c), v1tap_d(s1, s2, y, c),
                v1tap_d(s1, s2, y + 2, c));
}

// ── Exact border vertical, fp16 source, R=4 fused pair (levels 3+4) ──
__device__ __forceinline__ float4 v1tap_h4(const __half2* __restrict__ src, int q, int c2) {
    q = iclamp(q, 0, Hd - 1);
    int ym = iclamp(q - 4, 0, Hd - 1), yp = iclamp(q + 4, 0, Hd - 1);
    return vmix(ldh4(src + (size_t)ym * WH2 + c2), ldh4(src + (size_t)q * WH2 + c2),
                ldh4(src + (size_t)yp * WH2 + c2));
}
__device__ __forceinline__ float4 vv_exact_h4(const __half2* __restrict__ src, int y, int c2) {
    return vmix(v1tap_h4(src, y - 8, c2), v1tap_h4(src, y, c2), v1tap_h4(src, y + 8, c2));
}

// ── Exact border horizontal (full-width fp32 smem row, AB) ──
template <int RS>
__device__ __forceinline__ float hh_lh(const float* row, int q) {
    q = iclamp(q, 0, Wd - 1);
    return fmaf(0.25f, row[iclamp(q - RS, 0, Wd - 1)] + row[iclamp(q + RS, 0, Wd - 1)],
                0.5f * row[q]);
}
template <int RS>
__device__ __forceinline__ float hh_exact_px(const float* row, int p) {
    return fmaf(0.25f, hh_lh<RS>(row, iclamp(p - 2 * RS, 0, Wd - 1)) +
                        hh_lh<RS>(row, iclamp(p + 2 * RS, 0, Wd - 1)),
                0.5f * hh_lh<RS>(row, p));
}

// ── Exact border horizontal for CD tile rows, fp16 smem row ──
__device__ __forceinline__ float hh_lh4h(const __half* rh, int q, int off) {
    q = iclamp(q, 0, Wd - 1);
    return fmaf(0.25f, __half2float(rh[iclamp(q - 4, 0, Wd - 1) + off]) +
                        __half2float(rh[iclamp(q + 4, 0, Wd - 1) + off]),
                0.5f * __half2float(rh[q + off]));
}
__device__ __forceinline__ float hh_ex4h(const __half* rh, int p, int off) {
    return fmaf(0.25f, hh_lh4h(rh, iclamp(p - 8, 0, Wd - 1), off) +
                        hh_lh4h(rh, iclamp(p + 8, 0, Wd - 1), off),
                0.5f * hh_lh4h(rh, p, off));
}

// ───── Kernel A: d = hq - lq, levels 1+2 fused, 16-row band, fp16-packed window ─────
#define TH_A 16
#define NB_A (Hd / TH_A)   // 45
__global__ void __launch_bounds__(320, 3)
levelAB(const float4* __restrict__ hq4, const float4* __restrict__ lq4,
        __half2* __restrict__ dstD) {
    __shared__ float4 s[8 * WV];  // 40 KB
    const int c = threadIdx.x;
    const int y0 = blockIdx.x * TH_A;
    const int z = blockIdx.y;
    const float4* s1 = hq4 + (size_t)z * NPV;
    const float4* s2 = lq4 + (size_t)z * NPV;
    __half2* dst = dstD + (size_t)z * NPH2;

    const bool interior = (y0 >= 3) && (y0 + TH_A - 1 + 3 < Hd);
    const float4* p1 = s1 + (size_t)(y0 - 3) * WV + c;
    const float4* p2 = s2 + (size_t)(y0 - 3) * WV + c;
    uint2 w[7];  // fp16-packed sliding window (14 regs)
    if (interior) {
        #pragma unroll
        for (int i = 0; i < 7; i++)
            w[i] = pack4(fsub(__ldg(p1 + (size_t)i * WV), __ldg(p2 + (size_t)i * WV)));
    }

    #pragma unroll
    for (int ch = 0; ch < 2; ch++) {
        if (interior) {
            #pragma unroll
            for (int r = 0; r < 8; r++) {
                const int rr = ch * 8 + r;
                s[r * WV + c] = f7(unpack4(w[rr % 7]), unpack4(w[(rr + 1) % 7]),
                                   unpack4(w[(rr + 2) % 7]), unpack4(w[(rr + 3) % 7]),
                                   unpack4(w[(rr + 4) % 7]), unpack4(w[(rr + 5) % 7]),
                                   unpack4(w[(rr + 6) % 7]));
                if (rr < TH_A - 1)
                    w[rr % 7] = pack4(fsub(__ldg(p1 + (size_t)(7 + rr) * WV),
                                           __ldg(p2 + (size_t)(7 + rr) * WV)));
            }
        } else {
            #pragma unroll
            for (int r = 0; r < 8; r++)
                s[r * WV + c] = vv_exact_d(s1, s2, y0 + ch * 8 + r, c);
        }
        __syncthreads();
        #pragma unroll
        for (int r = 0; r < 8; r++) {
            const float4* row = s + r * WV;
            float4 o;
            if (c >= 1 && c <= WV - 2) {
                float4 L = row[c - 1], C = row[c], R = row[c + 1];
                o.x = t7(L.y, L.z, L.w, C.x, C.y, C.z, C.w);
                o.y = t7(L.z, L.w, C.x, C.y, C.z, C.w, R.x);
                o.z = t7(L.w, C.x, C.y, C.z, C.w, R.x, R.y);
                o.w = t7(C.x, C.y, C.z, C.w, R.x, R.y, R.z);
            } else {
                const float* rf = (const float*)row;
                int p0 = c * 4;
                o.x = hh_exact_px<1>(rf, p0);
                o.y = hh_exact_px<1>(rf, p0 + 1);
                o.z = hh_exact_px<1>(rf, p0 + 2);
                o.w = hh_exact_px<1>(rf, p0 + 3);
            }
            sth4(dst + (size_t)(y0 + ch * 8 + r) * WH2 + 2 * c, o);
        }
        __syncthreads();
    }
}

// ───── Kernel B: levels 3+4 fused on d, residue chains, fp16 smem + packed window ─────
#define TH_B 48
#define NB_B (Hd / TH_B)   // 15
#define TW_B 160
#define WT_B 166
#define SWH (WT_B * 2)     // half2 per smem row (332)
__global__ void __launch_bounds__(672)
levelCD(const __half2* __restrict__ srcD, __half2* __restrict__ dstD) {
    extern __shared__ __half2 vb[];  // [24][SWH] fp16 = 31872 B
    const int c = threadIdx.x;      // 0..167 (166..167 idle in vertical)
    const int rho = threadIdx.y;    // residue 0..3
    const int tx0 = blockIdx.x * TW_B;
    const int y0 = blockIdx.y * TH_B;
    const int z = blockIdx.z;
    const __half2* src = srcD + (size_t)z * NPH2;
    __half2* dst = dstD + (size_t)z * NPH2;

    const int jv = tx0 - 3 + c;
    const int c2 = 2 * iclamp(jv, 0, WV - 1);
    const bool interior = (y0 >= 12) && (y0 + 3 + 44 + 12 < Hd);  // uniform
    const __half2* p = src + (size_t)(y0 + rho - 12) * WH2 + c2;
    uint2 w[7];  // raw fp16 window (no conversion until use)
    if (interior && c < WT_B) {
        #pragma unroll
        for (int i = 0; i < 7; i++) w[i] = ldh4r(p + (size_t)(4 * i) * WH2);
    }

    #pragma unroll
    for (int ch = 0; ch < 2; ch++) {
        // phase 1: vertical fused pair -> fp16 smem
        if (c < WT_B) {
            if (interior) {
                #pragma unroll
                for (int k = 0; k < 6; k++) {
                    const int kk = ch * 6 + k;
                    sth4(&vb[(rho + 4 * k) * SWH + 2 * c],
                         f7(unpack4(w[kk % 7]), unpack4(w[(kk + 1) % 7]),
                            unpack4(w[(kk + 2) % 7]), unpack4(w[(kk + 3) % 7]),
                            unpack4(w[(kk + 4) % 7]), unpack4(w[(kk + 5) % 7]),
                            unpack4(w[(kk + 6) % 7])));
                    if (kk < 11) w[kk % 7] = ldh4r(p + (size_t)(4 * (7 + kk)) * WH2);
                }
            } else {
                #pragma unroll
                for (int k = 0; k < 6; k++)
                    sth4(&vb[(rho + 4 * k) * SWH + 2 * c],
                         vv_exact_h4(src, y0 + ch * 24 + rho + 4 * k, c2));
            }
        }
        __syncthreads();
        // phase 2: horizontal fused pair + fp16 store
        if (c >= 3 && c <= 162) {
            const int j = tx0 + c - 3;
            #pragma unroll
            for (int k = 0; k < 6; k++) {
                const int rr = ch * 24 + rho + 4 * k;
                const __half2* row = vb + (rho + 4 * k) * SWH;
                float4 o;
                if (j >= 3 && j <= WV - 4) {
                    o = f7(ldh4(row + 2 * (c - 3)), ldh4(row + 2 * (c - 2)),
                           ldh4(row + 2 * (c - 1)), ldh4(row + 2 * c),
                           ldh4(row + 2 * (c + 1)), ldh4(row + 2 * (c + 2)),
                           ldh4(row + 2 * (c + 3)));
                } else {
                    const __half* rh = (const __half*)row;
                    const int off = 12 - tx0 * 4;
                    const int p0 = j * 4;
                    o.x = hh_ex4h(rh, p0, off);
                    o.y = hh_ex4h(rh, p0 + 1, off);
                    o.z = hh_ex4h(rh, p0 + 2, off);
                    o.w = hh_ex4h(rh, p0 + 3, off);
                }
                sth4(dst + (size_t)(y0 + rr) * WH2 + 2 * j, o);
            }
        }
        __syncthreads();
    }
}

// ───── Kernel C: level 5 (R=16) direct (no smem, no syncs) + combine ─────
#define RF5 4
__global__ void __launch_bounds__(320)
final5(const __half2* __restrict__ lowD, const float4* __restrict__ hq4,
       float4* __restrict__ out) {
    const int c = threadIdx.x;
    const int y0 = blockIdx.x * RF5;
    const int z = blockIdx.y;
    const __half2* sD = lowD + (size_t)z * NPH2;
    const float4* hp = hq4 + (size_t)z * NPV;
    float4* op = out + (size_t)z * NPV;

    #pragma unroll
    for (int r = 0; r < RF5; r++) {
        const int y = y0 + r;
        const int ym = iclamp(y - 16, 0, Hd - 1);
        const int yp = iclamp(y + 16, 0, Hd - 1);
        const __half2* rm = sD + (size_t)ym * WH2;
        const __half2* rc = sD + (size_t)y * WH2;
        const __half2* rp = sD + (size_t)yp * WH2;

        // vertical taps at float4 cols c, c-4 (or 0), c+4 (or 319)
        const int cm = (c >= 4) ? (c - 4) : 0;
        const int cp = (c <= WV - 5) ? (c + 4) : (WV - 1);
        float4 Vc = vmix(ldh4(rm + 2 * c),  ldh4(rc + 2 * c),  ldh4(rp + 2 * c));
        float4 Vm = vmix(ldh4(rm + 2 * cm), ldh4(rc + 2 * cm), ldh4(rp + 2 * cm));
        float4 Vp = vmix(ldh4(rm + 2 * cp), ldh4(rc + 2 * cp), ldh4(rp + 2 * cp));
        if (c < 4) Vm = splat4(Vm.x);            // px clamp to 0
        if (c > WV - 5) Vp = splat4(Vp.w);       // px clamp to 1279
        float4 lo = vmix(Vm, Vc, Vp);

        float4 h = __ldg(hp + (size_t)y * WV + c);
        float4 o;
        o.x = fminf(fmaxf(h.x - lo.x, -1.0f), 1.0f);
        o.y = fminf(fmaxf(h.y - lo.y, -1.0f), 1.0f);
        o.z = fminf(fmaxf(h.z - lo.z, -1.0f), 1.0f);
        o.w = fminf(fmaxf(h.w - lo.w, -1.0f), 1.0f);
        op[(size_t)y * WV + c] = o;
    }
}

extern "C" void kernel_launch(void* const* d_in, const int* in_sizes, int n_in,
                              void* d_out, int out_size) {
    const float4* hq = (const float4*)d_in[0];
    const float4* lq = (const float4*)d_in[1];
    float4* out = (float4*)d_out;

    __half2 *A, *B;
    cudaGetSymbolAddress((void**)&A, g_bufA);
    cudaGetSymbolAddress((void**)&B, g_bufB);

    const int smemB = 24 * SWH * sizeof(__half2);  // 31872
    cudaFuncSetAttribute(levelCD, cudaFuncAttributeMaxDynamicSharedMemorySize, smemB);

    // levels 1+2 on d = hq - lq: fp32 inputs -> A (low2(d), fp16)
    levelAB<<<dim3(NB_A, PLANES), dim3(320, 1)>>>(hq, lq, A);
    // levels 3+4: A -> B (low4(d), fp16)
    levelCD<<<dim3(WV / TW_B, NB_B, PLANES), dim3(168, 4), smemB>>>(A, B);
    // level 5 + combine: out = clip(hq - low5(d)), direct, syncless
    final5<<<dim3(Hd / RF5, PLANES), dim3(320, 1)>>>(B, hq, out);
}